// round 3
// baseline (speedup 1.0000x reference)
#include <cuda_runtime.h>

// Shapes
#define T_DIM 32
#define B_DIM 512
#define H_DIM 300
#define TB    16384          // T*B
#define NROWS 163840         // TB*10  (rows indexed (t,b,k))

// Scratch (device globals — no allocation)
__device__ float g_Con [NROWS*300];   // cells output  [t,b,k,h]
__device__ float g_Con1[NROWS*300];   // con1          [t,b,k,h]
__device__ float g_fc1 [NROWS*200];   // fc1           [t,b,k,o]
__device__ float g_ht  [TB*300];      // htarget       [t,b,h]
__device__ float g_htF [TB*200];      // htarget@F1[300:]+b1
__device__ float g_wdyn[NROWS];
__device__ float g_den [TB];

__device__ __forceinline__ float sigm(float v){ return 1.f/(1.f+__expf(-v)); }

// ---------------------------------------------------------------------------
// cells: g = Wih[k] @ x[b,t,0:11,k] + b_ih + b_hh ; h = sig(o)*tanh(sig(i)*tanh(g))
// block: (tb-chunk of 32, k). Wih gate slices (i,g,o) staged in smem.
// ---------------------------------------------------------------------------
__global__ __launch_bounds__(320) void cells_kernel(
    const float* __restrict__ x, const float* __restrict__ Wih,
    const float* __restrict__ bih, const float* __restrict__ bhh)
{
  int k = blockIdx.y;
  __shared__ float sW[9900];   // 3 gates x 300 x 11
  __shared__ float sb[900];
  int base = k*13200;          // k*1200*11
  for (int idx=threadIdx.x; idx<3300; idx+=320){
    sW[idx]      = Wih[base + idx];          // gate i : rows 0..299
    sW[3300+idx] = Wih[base + 6600 + idx];   // gate g : rows 600..899
    sW[6600+idx] = Wih[base + 9900 + idx];   // gate o : rows 900..1199
  }
  for (int idx=threadIdx.x; idx<300; idx+=320){
    sb[idx]     = bih[k*1200+idx]     + bhh[k*1200+idx];
    sb[300+idx] = bih[k*1200+600+idx] + bhh[k*1200+600+idx];
    sb[600+idx] = bih[k*1200+900+idx] + bhh[k*1200+900+idx];
  }
  __syncthreads();
  int h = threadIdx.x;
  int tb0 = blockIdx.x*32;
  for (int tb=tb0; tb<tb0+32; tb++){
    int t = tb>>9, b = tb & 511;
    const float* xp = x + ((b*32+t)*28)*10 + k;   // x[b,t,i,k], i stride 10
    float xs[11];
    #pragma unroll
    for(int i=0;i<11;i++) xs[i] = __ldg(xp + i*10);
    if (h < 300){
      float gi=sb[h], gg=sb[300+h], go=sb[600+h];
      #pragma unroll
      for(int i=0;i<11;i++){
        gi = fmaf(sW[h*11+i],      xs[i], gi);
        gg = fmaf(sW[3300+h*11+i], xs[i], gg);
        go = fmaf(sW[6600+h*11+i], xs[i], go);
      }
      g_Con[(tb*10+k)*300+h] = sigm(go)*tanhf(sigm(gi)*tanhf(gg));
    }
  }
}

// ---------------------------------------------------------------------------
// target cell: h = sig(o)*tanh(sig(i)*tanh(g)),  g = extras[b,t,:4] @ Wt^T + bt
// ---------------------------------------------------------------------------
__global__ __launch_bounds__(256) void target_kernel(
    const float* __restrict__ extras, const float* __restrict__ Wt,
    const float* __restrict__ bti, const float* __restrict__ bth)
{
  int idx = blockIdx.x*blockDim.x+threadIdx.x;
  if (idx >= TB*300) return;
  int tb = idx/300, h = idx - tb*300;
  int t = tb>>9, b = tb&511;
  const float* e = extras + (b*32+t)*4;
  float e0=e[0], e1=e[1], e2=e[2], e3=e[3];
  const float* w = Wt + h*4;
  float gi = w[0]*e0+w[1]*e1+w[2]*e2+w[3]*e3 + bti[h]+bth[h];
  w = Wt + (600+h)*4;
  float gg = w[0]*e0+w[1]*e1+w[2]*e2+w[3]*e3 + bti[600+h]+bth[600+h];
  w = Wt + (900+h)*4;
  float go = w[0]*e0+w[1]*e1+w[2]*e2+w[3]*e3 + bti[900+h]+bth[900+h];
  g_ht[idx] = sigm(go)*tanhf(sigm(gi)*tanhf(gg));
}

// t=0: con1 = con0 (no wp transform)
__global__ void copy_con0(){
  int i = blockIdx.x*blockDim.x+threadIdx.x;
  if (i < 5120*300) g_Con1[i] = g_Con[i];
}

// ---------------------------------------------------------------------------
// Tiled GEMM 128x64x16, 256 threads, 8x4 per-thread tile.
// MODE 0: con1 = relu([Con_t | Con_{t-1}] @ wp^T + bp)          (K=600, N=300)
// MODE 1: htF  = ht @ F1[300:600] + b1                          (K=300, N=200)
// MODE 2: fc1  = relu(Con1 @ F1[0:300] + htF[row/10])           (K=300, N=200)
// ---------------------------------------------------------------------------
template<int MODE>
__global__ __launch_bounds__(256) void gemm_kernel(
    const float* __restrict__ Bm, const float* __restrict__ bias,
    int M, int N, int K)
{
  const float* A1; const float* A0 = nullptr; const float* rowadd = nullptr; float* C;
  if (MODE==0){ A1 = g_Con + 1536000; A0 = g_Con; C = g_Con1 + 1536000; }
  else if (MODE==1){ A1 = g_ht; C = g_htF; }
  else { A1 = g_Con1; rowadd = g_htF; C = g_fc1; }

  __shared__ float As[16][132];  // pad 4 -> float4-aligned, 2-way store conflicts only
  __shared__ float Bs[16][68];
  int tid = threadIdx.x;
  int tx = tid & 15, ty = tid >> 4;
  int m0 = blockIdx.y*128, n0 = blockIdx.x*64;
  float acc[8][4] = {};

  for (int k0=0; k0<K; k0+=16){
    #pragma unroll
    for (int l=0;l<8;l++){
      int idx = tid + l*256;
      int c = idx & 15, m = idx >> 4;
      int kk = k0 + c;
      float v = 0.f;
      if (kk < K){
        if (MODE==0) v = (kk < 300) ? A1[(m0+m)*300+kk] : A0[(m0+m)*300+(kk-300)];
        else         v = A1[(m0+m)*300+kk];
      }
      As[c][m] = v;
    }
    #pragma unroll
    for (int l=0;l<4;l++){
      int idx = tid + l*256;
      if (MODE==0){                       // B = wp^T : wp[n,kk], kk contiguous
        int n = idx >> 4, c = idx & 15;
        int kk = k0 + c;
        float v = 0.f;
        if (kk < K && (n0+n) < N) v = Bm[(n0+n)*600 + kk];
        Bs[c][n] = v;
      } else {                            // B row-major [K,200]
        int c = idx >> 6, n = idx & 63;
        int kk = k0 + c;
        float v = 0.f;
        if (kk < K && (n0+n) < N) v = Bm[kk*200 + (n0+n)];
        Bs[c][n] = v;
      }
    }
    __syncthreads();
    #pragma unroll
    for (int c=0;c<16;c++){
      float4 b4 = *(const float4*)&Bs[c][tx*4];
      float4 al = *(const float4*)&As[c][ty*8];
      float4 ah = *(const float4*)&As[c][ty*8+4];
      float av[8] = {al.x,al.y,al.z,al.w,ah.x,ah.y,ah.z,ah.w};
      float bv[4] = {b4.x,b4.y,b4.z,b4.w};
      #pragma unroll
      for(int i=0;i<8;i++)
        #pragma unroll
        for(int j=0;j<4;j++) acc[i][j] = fmaf(av[i], bv[j], acc[i][j]);
    }
    __syncthreads();
  }
  #pragma unroll
  for (int i=0;i<8;i++){
    int m = m0 + ty*8 + i;
    #pragma unroll
    for (int j=0;j<4;j++){
      int n = n0 + tx*4 + j;
      if (n < N){
        float v = acc[i][j];
        if (MODE==0)      v = fmaxf(v + bias[n], 0.f);
        else if (MODE==1) v = v + bias[n];
        else              v = fmaxf(v + rowadd[(m/10)*200 + n], 0.f);
        C[m*N + n] = v;
      }
    }
  }
}

// ---------------------------------------------------------------------------
// wdyn[r] = relu(fc1[r]·F2[:200] + x8*F2[200] + ang*F2[201] + b2); warp per row
// ---------------------------------------------------------------------------
__global__ __launch_bounds__(256) void wdyn_kernel(
    const float* __restrict__ x, const float* __restrict__ AngleM,
    const float* __restrict__ F2, const float* __restrict__ b2)
{
  int r = blockIdx.x*8 + (threadIdx.x>>5);
  int lane = threadIdx.x & 31;
  if (r >= NROWS) return;
  const float* f = g_fc1 + r*200;
  float s = 0.f;
  for (int o=lane; o<200; o+=32) s = fmaf(f[o], F2[o], s);
  #pragma unroll
  for (int off=16; off; off>>=1) s += __shfl_xor_sync(0xffffffffu, s, off);
  if (lane==0){
    int tb = r/10, k = r - tb*10;
    int t = tb>>9, b = tb&511;
    const float* xb = x + (b*32+t)*280;
    float x8  = xb[80+k];                                  // channel 8
    float ang = fabsf(xb[100+k] - AngleM[k]) * (1.f/360.f); // channel 10
    float w = s + x8*F2[200] + ang*F2[201] + b2[0];
    g_wdyn[r] = fmaxf(w, 0.f);
  }
}

__global__ void denom_kernel(){
  int tb = blockIdx.x*blockDim.x+threadIdx.x;
  if (tb >= TB) return;
  float s=0.f;
  #pragma unroll
  for(int k=0;k<10;k++) s += __expf(g_wdyn[tb*10+k]);
  g_den[tb]=s;
}

// ---------------------------------------------------------------------------
// final: scrambled softmax gather, cat, fuse, fusiondis, output + labels
// wa3 is the FLAT reshape of softmax([10,B]) into [B,1,10]:
//   wa3[b,k] = exp(wdyn[b_o,k_o])/den[b_o], j=b*10+k, k_o=j>>9, b_o=j&511
// ---------------------------------------------------------------------------
__global__ __launch_bounds__(128) void final_kernel(
    const float* __restrict__ x, const float* __restrict__ labels,
    const float* __restrict__ DisM, const float* __restrict__ fuse1,
    const float* __restrict__ biasf, const float* __restrict__ ff,
    const float* __restrict__ bff, const float* __restrict__ Wout,
    const float* __restrict__ biasout, const float* __restrict__ a,
    float* __restrict__ out, int out_size)
{
  int tb = blockIdx.x; int t=tb>>9, b=tb&511;
  __shared__ float wa[10], swA[10], cat[300], xw[17], mix[100];
  int tid = threadIdx.x;
  if (tid==0){
    float d[10], mx=-1e30f;
    #pragma unroll
    for(int i=0;i<10;i++){ d[i]=DisM[i]; mx=fmaxf(mx,d[i]); }
    float s=0.f;
    #pragma unroll
    for(int i=0;i<10;i++){ float e=__expf(d[i]-mx); swA[i]=e; s+=e; }
    float inv = 1.f/s;
    #pragma unroll
    for(int i=0;i<10;i++) swA[i]*=inv;
  }
  if (tid<10){
    int j = b*10+tid;
    int ko = j>>9, bo = j&511;
    wa[tid] = __expf(g_wdyn[(t*512+bo)*10+ko]) / g_den[t*512+bo];
  }
  __syncthreads();
  for (int h=tid; h<300; h+=128){
    float s=0.f;
    #pragma unroll
    for(int k=0;k<10;k++) s = fmaf(g_Con1[(tb*10+k)*300+h], wa[k], s);
    cat[h]=s;
  }
  if (tid<17){
    const float* xp = x + (b*32+t)*280 + (11+tid)*10;
    float s=0.f;
    #pragma unroll
    for(int k=0;k<10;k++) s = fmaf(xp[k], swA[k], s);
    xw[tid]=s;
  }
  __syncthreads();
  float aa = a[0];
  if (tid<100){
    float fu = biasf[tid];
    for(int h=0;h<300;h++) fu = fmaf(cat[h], fuse1[h*100+tid], fu);
    float fd = bff[tid];
    #pragma unroll
    for(int f=0;f<17;f++) fd = fmaf(ff[tid*17+f], xw[f], fd);
    mix[tid] = (aa*fu + (1.f-aa)*fd) * Wout[tid];
  }
  __syncthreads();
  if (tid==0){
    float s = biasout[0];
    for(int o=0;o<100;o++) s += mix[o];
    out[t*512+b] = s;
  }
  if (tid==1 && out_size >= 2*TB){
    out[TB + t*512+b] = labels[b*32+t];
  }
}

// ---------------------------------------------------------------------------
extern "C" void kernel_launch(void* const* d_in, const int* in_sizes, int n_in,
                              void* d_out, int out_size)
{
  const float* x      = (const float*)d_in[0];
  const float* labels = (const float*)d_in[1];
  const float* extras = (const float*)d_in[2];
  const float* DisM   = (const float*)d_in[3];
  const float* AngleM = (const float*)d_in[4];
  const float* Wih    = (const float*)d_in[5];
  const float* b_ih   = (const float*)d_in[6];
  const float* b_hh   = (const float*)d_in[7];
  const float* Wt     = (const float*)d_in[8];
  const float* bt_ih  = (const float*)d_in[9];
  const float* bt_hh  = (const float*)d_in[10];
  const float* wp     = (const float*)d_in[11];
  const float* bp     = (const float*)d_in[12];
  const float* F1     = (const float*)d_in[13];
  const float* b1     = (const float*)d_in[14];
  const float* F2     = (const float*)d_in[15];
  const float* b2     = (const float*)d_in[16];
  const float* ff     = (const float*)d_in[17];
  const float* bff    = (const float*)d_in[18];
  const float* fuse1  = (const float*)d_in[19];
  const float* biasf  = (const float*)d_in[20];
  const float* Wout   = (const float*)d_in[21];
  const float* biasout= (const float*)d_in[22];
  const float* a      = (const float*)d_in[23];
  float* out = (float*)d_out;

  cells_kernel<<<dim3(512,10),320>>>(x, Wih, b_ih, b_hh);
  target_kernel<<<(TB*300+255)/256,256>>>(extras, Wt, bt_ih, bt_hh);
  copy_con0<<<(1536000+255)/256,256>>>();
  // htF = ht @ F1[300:600] + b1           (M=16384,  N=200, K=300)
  gemm_kernel<1><<<dim3(4, TB/128),256>>>(F1 + 300*200, b1, TB, 200, 300);
  // con1 = relu([Con_t|Con_{t-1}] @ wp^T + bp)   (M=158720, N=300, K=600)
  gemm_kernel<0><<<dim3(5, (NROWS-5120)/128),256>>>(wp, bp, NROWS-5120, 300, 600);
  // fc1 = relu(Con1 @ F1[0:300] + htF)    (M=163840, N=200, K=300)
  gemm_kernel<2><<<dim3(4, NROWS/128),256>>>(F1, b1, NROWS, 200, 300);
  wdyn_kernel<<<NROWS/8, 256>>>(x, AngleM, F2, b2);
  denom_kernel<<<TB/256, 256>>>();
  final_kernel<<<TB, 128>>>(x, labels, DisM, fuse1, biasf, ff, bff,
                            Wout, biasout, a, out, out_size);
}

// round 5
// speedup vs baseline: 2.9087x; 2.9087x over previous
#include <cuda_runtime.h>
#include <cstdint>

// Shapes
#define T_DIM 32
#define B_DIM 512
#define H_DIM 300
#define TB    16384          // T*B
#define NROWS 163840         // TB*10

#define BM 128
#define BN 128
#define BK 16
#define NCH 38               // ceil(600/16)

// Scratch (device globals — no allocation)
__device__ float g_Con [NROWS*300];   // cells output [t,b,k,h] (tf32-rounded)
__device__ float g_Con1[NROWS*300];   // con1 (tf32-rounded)
__device__ float g_fc1 [NROWS*200];   // fc1 (fp32)
__device__ float g_ht  [TB*300];      // htarget (tf32-rounded)
__device__ float g_wdyn[NROWS];
__device__ float g_den [TB];
__device__ float g_wpT [600*300];     // wp^T, tf32-rounded, [kk][n]
__device__ float g_F1_r[600*200];     // F1 tf32-rounded, [kk][n]

__device__ __forceinline__ float to_tf32(float v){
  float r; asm("cvt.rna.tf32.f32 %0, %1;" : "=f"(r) : "f"(v)); return r;
}
__device__ __forceinline__ float sigm(float v){
  return __fdividef(1.f, 1.f + __expf(-v));
}
__device__ __forceinline__ float ftanh(float x){
  x = fminf(fmaxf(x, -15.f), 15.f);
  float e = __expf(2.f*x);
  return __fdividef(e - 1.f, e + 1.f);
}

// ---------------------------------------------------------------------------
// cells (outputs tf32-rounded)
// ---------------------------------------------------------------------------
__global__ __launch_bounds__(320) void cells_kernel(
    const float* __restrict__ x, const float* __restrict__ Wih,
    const float* __restrict__ bih, const float* __restrict__ bhh)
{
  int k = blockIdx.y;
  __shared__ float sW[9900];
  __shared__ float sb[900];
  int base = k*13200;
  for (int idx=threadIdx.x; idx<3300; idx+=320){
    sW[idx]      = Wih[base + idx];
    sW[3300+idx] = Wih[base + 6600 + idx];
    sW[6600+idx] = Wih[base + 9900 + idx];
  }
  for (int idx=threadIdx.x; idx<300; idx+=320){
    sb[idx]     = bih[k*1200+idx]     + bhh[k*1200+idx];
    sb[300+idx] = bih[k*1200+600+idx] + bhh[k*1200+600+idx];
    sb[600+idx] = bih[k*1200+900+idx] + bhh[k*1200+900+idx];
  }
  __syncthreads();
  int h = threadIdx.x;
  int tb0 = blockIdx.x*32;
  for (int tb=tb0; tb<tb0+32; tb++){
    int t = tb>>9, b = tb & 511;
    const float* xp = x + ((b*32+t)*28)*10 + k;
    float xs[11];
    #pragma unroll
    for(int i=0;i<11;i++) xs[i] = __ldg(xp + i*10);
    if (h < 300){
      float gi=sb[h], gg=sb[300+h], go=sb[600+h];
      #pragma unroll
      for(int i=0;i<11;i++){
        gi = fmaf(sW[h*11+i],      xs[i], gi);
        gg = fmaf(sW[3300+h*11+i], xs[i], gg);
        go = fmaf(sW[6600+h*11+i], xs[i], go);
      }
      g_Con[(tb*10+k)*300+h] = to_tf32(sigm(go)*ftanh(sigm(gi)*ftanh(gg)));
    }
  }
}

// ---------------------------------------------------------------------------
// target cell (outputs tf32-rounded)
// ---------------------------------------------------------------------------
__global__ __launch_bounds__(256) void target_kernel(
    const float* __restrict__ extras, const float* __restrict__ Wt,
    const float* __restrict__ bti, const float* __restrict__ bth)
{
  int idx = blockIdx.x*blockDim.x+threadIdx.x;
  if (idx >= TB*300) return;
  int tb = idx/300, h = idx - tb*300;
  int t = tb>>9, b = tb&511;
  const float* e = extras + (b*32+t)*4;
  float e0=e[0], e1=e[1], e2=e[2], e3=e[3];
  const float* w = Wt + h*4;
  float gi = w[0]*e0+w[1]*e1+w[2]*e2+w[3]*e3 + bti[h]+bth[h];
  w = Wt + (600+h)*4;
  float gg = w[0]*e0+w[1]*e1+w[2]*e2+w[3]*e3 + bti[600+h]+bth[600+h];
  w = Wt + (900+h)*4;
  float go = w[0]*e0+w[1]*e1+w[2]*e2+w[3]*e3 + bti[900+h]+bth[900+h];
  g_ht[idx] = to_tf32(sigm(go)*ftanh(sigm(gi)*ftanh(gg)));
}

__global__ void copy_con0(){
  int i = blockIdx.x*blockDim.x+threadIdx.x;
  if (i < 5120*300) g_Con1[i] = g_Con[i];
}

// wp^T (tf32) and F1 (tf32)
__global__ void round_weights(const float* __restrict__ wp, const float* __restrict__ F1){
  int i = blockIdx.x*blockDim.x+threadIdx.x;
  if (i < 180000){
    int kk = i/300, n = i - kk*300;
    g_wpT[i] = to_tf32(wp[n*600 + kk]);
  }
  if (i < 120000) g_F1_r[i] = to_tf32(F1[i]);
}

// ---------------------------------------------------------------------------
// tf32 mma.sync GEMM: 128x128 tile, BK=16, double-buffered, 8 warps (2x4).
// MODE 0: con1 = relu([Con_t|Con_{t-1}] @ wpT + bp)    M=158720, N=300, K=600
// MODE 2: fc1  = relu([Con1|ht(m/10)] @ F1 + b1)       M=163840, N=200, K=600
// ---------------------------------------------------------------------------
template<int MODE>
__device__ __forceinline__ float4 loadA4(int m, int kk){
  const float4 z = make_float4(0.f,0.f,0.f,0.f);
  if (MODE==0){
    if (kk < 300)      return *(const float4*)&g_Con[1536000 + m*300 + kk];
    else if (kk < 600) return *(const float4*)&g_Con[m*300 + (kk-300)];
    return z;
  } else {
    if (kk < 300)      return *(const float4*)&g_Con1[m*300 + kk];
    else if (kk < 600) return *(const float4*)&g_ht[(m/10)*300 + (kk-300)];
    return z;
  }
}

template<int MODE>
__global__ __launch_bounds__(256,2) void mma_gemm(const float* __restrict__ bias, int Ntot)
{
  __shared__ float As[2][BM][20];     // [m][k], stride 20 -> conflict-free frags
  __shared__ float Bs[2][BK][136];    // [k][n], stride 136

  const float* Bsrc = (MODE==0) ? g_wpT : g_F1_r;
  const int ldb = (MODE==0) ? 300 : 200;
  float* Cptr = (MODE==0) ? (g_Con1 + 1536000) : g_fc1;

  int tid = threadIdx.x, lane = tid&31, wid = tid>>5;
  int warpM = wid>>2, warpN = wid&3;          // 2 x 4
  int g = lane>>2, tg = lane&3;
  int m0 = blockIdx.y*BM, n0 = blockIdx.x*BN;

  // ldg index precompute
  int am[2], ac4[2], bk[2], bn[2];
  #pragma unroll
  for (int j=0;j<2;j++){
    int idx = tid + j*256;
    am[j] = idx>>2;  ac4[j] = (idx&3)*4;
    bk[j] = idx>>5;  bn[j]  = (idx&31)*4;
  }

  float acc[4][4][4];
  #pragma unroll
  for(int i=0;i<4;i++) for(int jn=0;jn<4;jn++) for(int r=0;r<4;r++) acc[i][jn][r]=0.f;

  float4 aR[2], bR[2];
  const float4 z4 = make_float4(0.f,0.f,0.f,0.f);

  // prefetch chunk 0
  #pragma unroll
  for (int j=0;j<2;j++){
    aR[j] = loadA4<MODE>(m0+am[j], ac4[j]);
    int kk = bk[j], n = n0+bn[j];
    bR[j] = (kk<600 && n<Ntot) ? *(const float4*)&Bsrc[kk*ldb + n] : z4;
  }
  #pragma unroll
  for (int j=0;j<2;j++){
    *(float4*)&As[0][am[j]][ac4[j]] = aR[j];
    *(float4*)&Bs[0][bk[j]][bn[j]]  = bR[j];
  }
  __syncthreads();

  for (int c=0; c<NCH; c++){
    int buf = c & 1;
    // prefetch c+1
    if (c+1 < NCH){
      int kk0 = (c+1)*BK;
      #pragma unroll
      for (int j=0;j<2;j++){
        aR[j] = loadA4<MODE>(m0+am[j], kk0 + ac4[j]);
        int kk = kk0 + bk[j], n = n0+bn[j];
        bR[j] = (kk<600 && n<Ntot) ? *(const float4*)&Bsrc[kk*ldb + n] : z4;
      }
    }
    // compute on buf
    #pragma unroll
    for (int ks=0; ks<2; ks++){
      int kb = ks*8;
      uint32_t af[4][4];
      #pragma unroll
      for (int mi=0; mi<4; mi++){
        int mr = warpM*64 + mi*16;
        af[mi][0] = __float_as_uint(As[buf][mr+g  ][kb+tg  ]);
        af[mi][1] = __float_as_uint(As[buf][mr+g+8][kb+tg  ]);
        af[mi][2] = __float_as_uint(As[buf][mr+g  ][kb+tg+4]);
        af[mi][3] = __float_as_uint(As[buf][mr+g+8][kb+tg+4]);
      }
      uint32_t bf[4][2];
      #pragma unroll
      for (int ni=0; ni<4; ni++){
        int nc = warpN*32 + ni*8;
        bf[ni][0] = __float_as_uint(Bs[buf][kb+tg  ][nc+g]);
        bf[ni][1] = __float_as_uint(Bs[buf][kb+tg+4][nc+g]);
      }
      #pragma unroll
      for (int mi=0; mi<4; mi++)
        #pragma unroll
        for (int ni=0; ni<4; ni++){
          asm volatile(
            "mma.sync.aligned.m16n8k8.row.col.f32.tf32.tf32.f32 "
            "{%0,%1,%2,%3}, {%4,%5,%6,%7}, {%8,%9}, {%0,%1,%2,%3};"
            : "+f"(acc[mi][ni][0]), "+f"(acc[mi][ni][1]),
              "+f"(acc[mi][ni][2]), "+f"(acc[mi][ni][3])
            : "r"(af[mi][0]), "r"(af[mi][1]), "r"(af[mi][2]), "r"(af[mi][3]),
              "r"(bf[ni][0]), "r"(bf[ni][1]));
        }
    }
    // stage c+1
    if (c+1 < NCH){
      int nbuf = buf ^ 1;
      #pragma unroll
      for (int j=0;j<2;j++){
        *(float4*)&As[nbuf][am[j]][ac4[j]] = aR[j];
        *(float4*)&Bs[nbuf][bk[j]][bn[j]]  = bR[j];
      }
    }
    __syncthreads();
  }

  // epilogue: bias + relu (+ tf32 round for MODE 0), float2 stores
  #pragma unroll
  for (int mi=0; mi<4; mi++){
    #pragma unroll
    for (int ni=0; ni<4; ni++){
      int row = m0 + warpM*64 + mi*16 + g;
      int col = n0 + warpN*32 + ni*8 + tg*2;
      if (col < Ntot){
        float b0v = bias[col], b1v = bias[col+1];
        float v0 = fmaxf(acc[mi][ni][0] + b0v, 0.f);
        float v1 = fmaxf(acc[mi][ni][1] + b1v, 0.f);
        float v2 = fmaxf(acc[mi][ni][2] + b0v, 0.f);
        float v3 = fmaxf(acc[mi][ni][3] + b1v, 0.f);
        if (MODE==0){ v0=to_tf32(v0); v1=to_tf32(v1); v2=to_tf32(v2); v3=to_tf32(v3); }
        *(float2*)&Cptr[row*Ntot + col]     = make_float2(v0, v1);
        *(float2*)&Cptr[(row+8)*Ntot + col] = make_float2(v2, v3);
      }
    }
  }
}

// ---------------------------------------------------------------------------
// wdyn: relu(fc1·F2[:200] + x8*F2[200] + ang*F2[201] + b2); warp per row
// ---------------------------------------------------------------------------
__global__ __launch_bounds__(256) void wdyn_kernel(
    const float* __restrict__ x, const float* __restrict__ AngleM,
    const float* __restrict__ F2, const float* __restrict__ b2)
{
  int r = blockIdx.x*8 + (threadIdx.x>>5);
  int lane = threadIdx.x & 31;
  if (r >= NROWS) return;
  const float* f = g_fc1 + r*200;
  float s = 0.f;
  for (int o=lane; o<200; o+=32) s = fmaf(f[o], F2[o], s);
  #pragma unroll
  for (int off=16; off; off>>=1) s += __shfl_xor_sync(0xffffffffu, s, off);
  if (lane==0){
    int tb = r/10, k = r - tb*10;
    int t = tb>>9, b = tb&511;
    const float* xb = x + (b*32+t)*280;
    float x8  = xb[80+k];
    float ang = fabsf(xb[100+k] - AngleM[k]) * (1.f/360.f);
    float w = s + x8*F2[200] + ang*F2[201] + b2[0];
    g_wdyn[r] = fmaxf(w, 0.f);
  }
}

__global__ void denom_kernel(){
  int tb = blockIdx.x*blockDim.x+threadIdx.x;
  if (tb >= TB) return;
  float s=0.f;
  #pragma unroll
  for(int k=0;k<10;k++) s += __expf(g_wdyn[tb*10+k]);
  g_den[tb]=s;
}

// ---------------------------------------------------------------------------
// final: scrambled softmax gather, cat, fuse, fusiondis, output + labels
// ---------------------------------------------------------------------------
__global__ __launch_bounds__(128) void final_kernel(
    const float* __restrict__ x, const float* __restrict__ labels,
    const float* __restrict__ DisM, const float* __restrict__ fuse1,
    const float* __restrict__ biasf, const float* __restrict__ ff,
    const float* __restrict__ bff, const float* __restrict__ Wout,
    const float* __restrict__ biasout, const float* __restrict__ a,
    float* __restrict__ out, int out_size)
{
  int tb = blockIdx.x; int t=tb>>9, b=tb&511;
  __shared__ float wa[10], swA[10], cat[300], xw[17], mix[100];
  int tid = threadIdx.x;
  if (tid==0){
    float d[10], mx=-1e30f;
    #pragma unroll
    for(int i=0;i<10;i++){ d[i]=DisM[i]; mx=fmaxf(mx,d[i]); }
    float s=0.f;
    #pragma unroll
    for(int i=0;i<10;i++){ float e=__expf(d[i]-mx); swA[i]=e; s+=e; }
    float inv = 1.f/s;
    #pragma unroll
    for(int i=0;i<10;i++) swA[i]*=inv;
  }
  if (tid<10){
    int j = b*10+tid;
    int ko = j>>9, bo = j&511;
    wa[tid] = __expf(g_wdyn[(t*512+bo)*10+ko]) / g_den[t*512+bo];
  }
  __syncthreads();
  for (int h=tid; h<300; h+=128){
    float s=0.f;
    #pragma unroll
    for(int k=0;k<10;k++) s = fmaf(g_Con1[(tb*10+k)*300+h], wa[k], s);
    cat[h]=s;
  }
  if (tid<17){
    const float* xp = x + (b*32+t)*280 + (11+tid)*10;
    float s=0.f;
    #pragma unroll
    for(int k=0;k<10;k++) s = fmaf(xp[k], swA[k], s);
    xw[tid]=s;
  }
  __syncthreads();
  float aa = a[0];
  if (tid<100){
    float fu = biasf[tid];
    for(int h=0;h<300;h++) fu = fmaf(cat[h], fuse1[h*100+tid], fu);
    float fd = bff[tid];
    #pragma unroll
    for(int f=0;f<17;f++) fd = fmaf(ff[tid*17+f], xw[f], fd);
    mix[tid] = (aa*fu + (1.f-aa)*fd) * Wout[tid];
  }
  __syncthreads();
  if (tid==0){
    float s = biasout[0];
    for(int o=0;o<100;o++) s += mix[o];
    out[t*512+b] = s;
  }
  if (tid==1 && out_size >= 2*TB){
    out[TB + t*512+b] = labels[b*32+t];
  }
}

// ---------------------------------------------------------------------------
extern "C" void kernel_launch(void* const* d_in, const int* in_sizes, int n_in,
                              void* d_out, int out_size)
{
  const float* x      = (const float*)d_in[0];
  const float* labels = (const float*)d_in[1];
  const float* extras = (const float*)d_in[2];
  const float* DisM   = (const float*)d_in[3];
  const float* AngleM = (const float*)d_in[4];
  const float* Wih    = (const float*)d_in[5];
  const float* b_ih   = (const float*)d_in[6];
  const float* b_hh   = (const float*)d_in[7];
  const float* Wt     = (const float*)d_in[8];
  const float* bt_ih  = (const float*)d_in[9];
  const float* bt_hh  = (const float*)d_in[10];
  const float* wp     = (const float*)d_in[11];
  const float* bp     = (const float*)d_in[12];
  const float* F1     = (const float*)d_in[13];
  const float* b1     = (const float*)d_in[14];
  const float* F2     = (const float*)d_in[15];
  const float* b2     = (const float*)d_in[16];
  const float* ff     = (const float*)d_in[17];
  const float* bff    = (const float*)d_in[18];
  const float* fuse1  = (const float*)d_in[19];
  const float* biasf  = (const float*)d_in[20];
  const float* Wout   = (const float*)d_in[21];
  const float* biasout= (const float*)d_in[22];
  const float* a      = (const float*)d_in[23];
  float* out = (float*)d_out;

  round_weights<<<(180000+255)/256,256>>>(wp, F1);
  cells_kernel<<<dim3(512,10),320>>>(x, Wih, b_ih, b_hh);
  target_kernel<<<(TB*300+255)/256,256>>>(extras, Wt, bt_ih, bt_hh);
  copy_con0<<<(1536000+255)/256,256>>>();
  // con1 = relu([Con_t|Con_{t-1}] @ wp^T + bp)   M=158720 (1240), N=300 (3)
  mma_gemm<0><<<dim3(3,1240),256>>>(bp, 300);
  // fc1 = relu([Con1|ht] @ F1 + b1)              M=163840 (1280), N=200 (2)
  mma_gemm<2><<<dim3(2,1280),256>>>(b1, 200);
  wdyn_kernel<<<NROWS/8, 256>>>(x, AngleM, F2, b2);
  denom_kernel<<<TB/256, 256>>>();
  final_kernel<<<TB, 128>>>(x, labels, DisM, fuse1, biasf, ff, bff,
                            Wout, biasout, a, out, out_size);
}

// round 6
// speedup vs baseline: 2.9850x; 1.0262x over previous
#include <cuda_runtime.h>
#include <cstdint>

// Shapes
#define T_DIM 32
#define B_DIM 512
#define H_DIM 300
#define TB    16384          // T*B
#define NROWS 163840         // TB*10

#define BM 128
#define BK 16
#define NCH 38               // ceil(600/16)

// Scratch (device globals — no allocation)
__device__ float g_Con [NROWS*300];   // cells output [t,b,k,h] (tf32-rounded)
__device__ float g_Con1[NROWS*300];   // con1 (tf32-rounded)
__device__ float g_ht  [TB*300];      // htarget (tf32-rounded)
__device__ float g_wdyn[NROWS];
__device__ float g_den [TB];
__device__ float g_wpT [600*300];     // wp^T, tf32-rounded, [kk][n]
__device__ float g_F1_r[600*200];     // F1 tf32-rounded, [kk][n]

__device__ __forceinline__ float to_tf32(float v){
  float r; asm("cvt.rna.tf32.f32 %0, %1;" : "=f"(r) : "f"(v)); return r;
}
__device__ __forceinline__ float ftanh(float x){
  float r; asm("tanh.approx.f32 %0, %1;" : "=f"(r) : "f"(x)); return r;
}
__device__ __forceinline__ float fsig(float x){
  return fmaf(ftanh(0.5f*x), 0.5f, 0.5f);
}

// ---------------------------------------------------------------------------
// cells (outputs tf32-rounded)
// ---------------------------------------------------------------------------
__global__ __launch_bounds__(320) void cells_kernel(
    const float* __restrict__ x, const float* __restrict__ Wih,
    const float* __restrict__ bih, const float* __restrict__ bhh)
{
  int k = blockIdx.y;
  __shared__ float sW[9900];
  __shared__ float sb[900];
  int base = k*13200;
  for (int idx=threadIdx.x; idx<3300; idx+=320){
    sW[idx]      = Wih[base + idx];
    sW[3300+idx] = Wih[base + 6600 + idx];
    sW[6600+idx] = Wih[base + 9900 + idx];
  }
  for (int idx=threadIdx.x; idx<300; idx+=320){
    sb[idx]     = bih[k*1200+idx]     + bhh[k*1200+idx];
    sb[300+idx] = bih[k*1200+600+idx] + bhh[k*1200+600+idx];
    sb[600+idx] = bih[k*1200+900+idx] + bhh[k*1200+900+idx];
  }
  __syncthreads();
  int h = threadIdx.x;
  int tb0 = blockIdx.x*32;
  for (int tb=tb0; tb<tb0+32; tb++){
    int t = tb>>9, b = tb & 511;
    const float* xp = x + ((b*32+t)*28)*10 + k;
    float xs[11];
    #pragma unroll
    for(int i=0;i<11;i++) xs[i] = __ldg(xp + i*10);
    if (h < 300){
      float gi=sb[h], gg=sb[300+h], go=sb[600+h];
      #pragma unroll
      for(int i=0;i<11;i++){
        gi = fmaf(sW[h*11+i],      xs[i], gi);
        gg = fmaf(sW[3300+h*11+i], xs[i], gg);
        go = fmaf(sW[6600+h*11+i], xs[i], go);
      }
      g_Con[(tb*10+k)*300+h] = to_tf32(fsig(go)*ftanh(fsig(gi)*ftanh(gg)));
    }
  }
}

// ---------------------------------------------------------------------------
// target cell (outputs tf32-rounded)
// ---------------------------------------------------------------------------
__global__ __launch_bounds__(256) void target_kernel(
    const float* __restrict__ extras, const float* __restrict__ Wt,
    const float* __restrict__ bti, const float* __restrict__ bth)
{
  int idx = blockIdx.x*blockDim.x+threadIdx.x;
  if (idx >= TB*300) return;
  int tb = idx/300, h = idx - tb*300;
  int t = tb>>9, b = tb&511;
  const float* e = extras + (b*32+t)*4;
  float e0=e[0], e1=e[1], e2=e[2], e3=e[3];
  const float* w = Wt + h*4;
  float gi = w[0]*e0+w[1]*e1+w[2]*e2+w[3]*e3 + bti[h]+bth[h];
  w = Wt + (600+h)*4;
  float gg = w[0]*e0+w[1]*e1+w[2]*e2+w[3]*e3 + bti[600+h]+bth[600+h];
  w = Wt + (900+h)*4;
  float go = w[0]*e0+w[1]*e1+w[2]*e2+w[3]*e3 + bti[900+h]+bth[900+h];
  g_ht[idx] = to_tf32(fsig(go)*ftanh(fsig(gi)*ftanh(gg)));
}

__global__ void copy_con0(){
  int i = blockIdx.x*blockDim.x+threadIdx.x;
  if (i < 384000) ((float4*)g_Con1)[i] = ((const float4*)g_Con)[i];
}

// wp^T (tf32) and F1 (tf32)
__global__ void round_weights(const float* __restrict__ wp, const float* __restrict__ F1){
  int i = blockIdx.x*blockDim.x+threadIdx.x;
  if (i < 180000){
    int kk = i/300, n = i - kk*300;
    g_wpT[i] = to_tf32(wp[n*600 + kk]);
  }
  if (i < 120000) g_F1_r[i] = to_tf32(F1[i]);
}

// ---------------------------------------------------------------------------
// tf32 mma.sync GEMM, 128xBN tile, BK=16, double-buffered, 8 warps (2x4).
// MODE 0: con1 = relu([Con_t|Con_{t-1}] @ wpT + bp)  M=158720, N=300, K=600, BN=160
// MODE 2: wdyn from fc1=relu([Con1|ht] @ F1 + b1)    M=163840, N=200, K=600, BN=224
//   (fc1 never materialized: epilogue computes relu(fc1)·F2 + extras -> g_wdyn)
// Dynamic smem: As [2][BM][20] then Bs [2][BK][BN+8].
// ---------------------------------------------------------------------------
template<int MODE>
__global__ __launch_bounds__(256) void mma_gemm(
    const float* __restrict__ bias, int Ntot,
    const float* __restrict__ x, const float* __restrict__ AngleM,
    const float* __restrict__ F2, const float* __restrict__ b2)
{
  constexpr int BN  = (MODE==0) ? 160 : 224;
  constexpr int NI  = (MODE==0) ? 5   : 7;      // per-warp n tiles of 8
  constexpr int WNW = BN/4;                     // warp n width (40 / 56)
  constexpr int BST = BN + 8;                   // Bs stride
  constexpr int TOT4 = BK*BN/4;                 // B float4s per chunk (640 / 896)
  constexpr int BIT  = (TOT4 + 255)/256;        // B stage iters (3 / 4)

  extern __shared__ float sm[];
  float* As = sm;                    // [2][BM][20]
  float* Bs = sm + 2*BM*20;          // [2][BK][BST]
  __shared__ float sF2[224];
  __shared__ float sdyn[BM];

  const float* Bsrc = (MODE==0) ? g_wpT : g_F1_r;
  const int ldb = (MODE==0) ? 300 : 200;

  int tid = threadIdx.x, lane = tid&31, wid = tid>>5;
  int warpM = wid>>2, warpN = wid&3;
  int g = lane>>2, tg = lane&3;
  int m0 = blockIdx.y*BM, n0 = blockIdx.x*BN;

  if (MODE==2){
    if (tid < 224) sF2[tid] = (tid < 200) ? F2[tid] : 0.f;
    if (tid < BM)  sdyn[tid] = 0.f;
  }

  // A ldg index precompute (2 iters cover 512 float4)
  int am[2], ac4[2];
  long aoff[2][2];                  // [j][0]=first-half row base, [1]=second
  #pragma unroll
  for (int j=0;j<2;j++){
    int idx = tid + j*256;
    am[j] = idx>>2;  ac4[j] = (idx&3)*4;
    int m = m0 + am[j];
    if (MODE==0){ aoff[j][0] = 1536000L + (long)m*300; aoff[j][1] = (long)m*300; }
    else        { aoff[j][0] = (long)m*300;            aoff[j][1] = (long)(m/10)*300; }
  }
  // B ldg index precompute
  int bkk[BIT], bn4[BIT];
  #pragma unroll
  for (int j=0;j<BIT;j++){
    int idx = tid + j*256;
    bkk[j] = idx / WNW; bn4[j] = (idx - bkk[j]*WNW)*4;
  }

  float acc[4][NI][4];
  #pragma unroll
  for(int i=0;i<4;i++) for(int jn=0;jn<NI;jn++) for(int r=0;r<4;r++) acc[i][jn][r]=0.f;

  const float4 z4 = make_float4(0.f,0.f,0.f,0.f);
  float4 aR[2], bR[BIT];

  auto fetchA = [&](int j, int kk)->float4{
    if (kk < 300)      return *(const float4*)&g_Con[aoff[j][0] + kk];
    else if (kk < 600) return (MODE==0)
        ? *(const float4*)&g_Con[aoff[j][1] + (kk-300)]
        : ( (MODE==2) ? *(const float4*)&g_ht[aoff[j][1] + (kk-300)]
                      : z4 );
    return z4;
  };
  // MODE 2 first half reads Con1:
  auto fetchA2 = [&](int j, int kk)->float4{
    if (MODE==0) return fetchA(j, kk);
    if (kk < 300)      return *(const float4*)&g_Con1[aoff[j][0] + kk];
    else if (kk < 600) return *(const float4*)&g_ht [aoff[j][1] + (kk-300)];
    return z4;
  };

  // prefetch chunk 0
  #pragma unroll
  for (int j=0;j<2;j++) aR[j] = fetchA2(j, ac4[j]);
  #pragma unroll
  for (int j=0;j<BIT;j++){
    int idx = tid + j*256;
    int kk = bkk[j], n = n0 + bn4[j];
    bR[j] = (idx<TOT4 && kk<600 && n<Ntot) ? *(const float4*)&Bsrc[kk*ldb + n] : z4;
  }
  #pragma unroll
  for (int j=0;j<2;j++) *(float4*)&As[(0*BM+am[j])*20 + ac4[j]] = aR[j];
  #pragma unroll
  for (int j=0;j<BIT;j++){
    int idx = tid + j*256;
    if (idx<TOT4) *(float4*)&Bs[(0*BK+bkk[j])*BST + bn4[j]] = bR[j];
  }
  __syncthreads();

  for (int c=0; c<NCH; c++){
    int buf = c & 1;
    if (c+1 < NCH){
      int kk0 = (c+1)*BK;
      #pragma unroll
      for (int j=0;j<2;j++) aR[j] = fetchA2(j, kk0 + ac4[j]);
      #pragma unroll
      for (int j=0;j<BIT;j++){
        int idx = tid + j*256;
        int kk = kk0 + bkk[j], n = n0 + bn4[j];
        bR[j] = (idx<TOT4 && kk<600 && n<Ntot) ? *(const float4*)&Bsrc[kk*ldb + n] : z4;
      }
    }
    #pragma unroll
    for (int ks=0; ks<2; ks++){
      int kb = ks*8;
      uint32_t af[4][4];
      #pragma unroll
      for (int mi=0; mi<4; mi++){
        int mr = warpM*64 + mi*16;
        af[mi][0] = __float_as_uint(As[(buf*BM + mr+g  )*20 + kb+tg  ]);
        af[mi][1] = __float_as_uint(As[(buf*BM + mr+g+8)*20 + kb+tg  ]);
        af[mi][2] = __float_as_uint(As[(buf*BM + mr+g  )*20 + kb+tg+4]);
        af[mi][3] = __float_as_uint(As[(buf*BM + mr+g+8)*20 + kb+tg+4]);
      }
      uint32_t bf[NI][2];
      #pragma unroll
      for (int ni=0; ni<NI; ni++){
        int nc = warpN*WNW + ni*8;
        bf[ni][0] = __float_as_uint(Bs[(buf*BK + kb+tg  )*BST + nc+g]);
        bf[ni][1] = __float_as_uint(Bs[(buf*BK + kb+tg+4)*BST + nc+g]);
      }
      #pragma unroll
      for (int mi=0; mi<4; mi++)
        #pragma unroll
        for (int ni=0; ni<NI; ni++){
          asm volatile(
            "mma.sync.aligned.m16n8k8.row.col.f32.tf32.tf32.f32 "
            "{%0,%1,%2,%3}, {%4,%5,%6,%7}, {%8,%9}, {%0,%1,%2,%3};"
            : "+f"(acc[mi][ni][0]), "+f"(acc[mi][ni][1]),
              "+f"(acc[mi][ni][2]), "+f"(acc[mi][ni][3])
            : "r"(af[mi][0]), "r"(af[mi][1]), "r"(af[mi][2]), "r"(af[mi][3]),
              "r"(bf[ni][0]), "r"(bf[ni][1]));
        }
    }
    if (c+1 < NCH){
      int nbuf = buf ^ 1;
      #pragma unroll
      for (int j=0;j<2;j++) *(float4*)&As[(nbuf*BM+am[j])*20 + ac4[j]] = aR[j];
      #pragma unroll
      for (int j=0;j<BIT;j++){
        int idx = tid + j*256;
        if (idx<TOT4) *(float4*)&Bs[(nbuf*BK+bkk[j])*BST + bn4[j]] = bR[j];
      }
    }
    __syncthreads();
  }

  if (MODE==0){
    // epilogue: bias + relu + tf32 round, float2 stores to Con1
    float* Cptr = g_Con1 + 1536000;
    #pragma unroll
    for (int mi=0; mi<4; mi++){
      #pragma unroll
      for (int ni=0; ni<NI; ni++){
        int row = m0 + warpM*64 + mi*16 + g;
        int col = n0 + warpN*WNW + ni*8 + tg*2;
        if (col < Ntot){
          float b0v = bias[col], b1v = bias[col+1];
          float v0 = to_tf32(fmaxf(acc[mi][ni][0] + b0v, 0.f));
          float v1 = to_tf32(fmaxf(acc[mi][ni][1] + b1v, 0.f));
          float v2 = to_tf32(fmaxf(acc[mi][ni][2] + b0v, 0.f));
          float v3 = to_tf32(fmaxf(acc[mi][ni][3] + b1v, 0.f));
          *(float2*)&Cptr[(long)row*Ntot + col]     = make_float2(v0, v1);
          *(float2*)&Cptr[(long)(row+8)*Ntot + col] = make_float2(v2, v3);
        }
      }
    }
  } else {
    // fused wdyn: per-row dot of relu(fc1+bias) with F2[:200]
    #pragma unroll
    for (int mi=0; mi<4; mi++){
      float p0 = 0.f, p1 = 0.f;
      #pragma unroll
      for (int ni=0; ni<NI; ni++){
        int col = n0 + warpN*WNW + ni*8 + tg*2;
        if (col < Ntot){
          float b0v = bias[col], b1v = bias[col+1];
          float f20 = sF2[col], f21 = sF2[col+1];
          p0 = fmaf(fmaxf(acc[mi][ni][0] + b0v, 0.f), f20, p0);
          p0 = fmaf(fmaxf(acc[mi][ni][1] + b1v, 0.f), f21, p0);
          p1 = fmaf(fmaxf(acc[mi][ni][2] + b0v, 0.f), f20, p1);
          p1 = fmaf(fmaxf(acc[mi][ni][3] + b1v, 0.f), f21, p1);
        }
      }
      p0 += __shfl_xor_sync(0xffffffffu, p0, 1);
      p0 += __shfl_xor_sync(0xffffffffu, p0, 2);
      p1 += __shfl_xor_sync(0xffffffffu, p1, 1);
      p1 += __shfl_xor_sync(0xffffffffu, p1, 2);
      if (tg == 0){
        int lr = warpM*64 + mi*16 + g;
        atomicAdd(&sdyn[lr], p0);
        atomicAdd(&sdyn[lr+8], p1);
      }
    }
    __syncthreads();
    if (tid < BM){
      int r = m0 + tid;
      int tb = r/10, k = r - tb*10;
      int t = tb>>9, b = tb&511;
      const float* xb = x + (b*32+t)*280;
      float x8  = xb[80+k];
      float ang = fabsf(xb[100+k] - AngleM[k]) * (1.f/360.f);
      float w = sdyn[tid] + x8*F2[200] + ang*F2[201] + b2[0];
      g_wdyn[r] = fmaxf(w, 0.f);
    }
  }
}

__global__ void denom_kernel(){
  int tb = blockIdx.x*blockDim.x+threadIdx.x;
  if (tb >= TB) return;
  float s=0.f;
  #pragma unroll
  for(int k=0;k<10;k++) s += __expf(g_wdyn[tb*10+k]);
  g_den[tb]=s;
}

// ---------------------------------------------------------------------------
// final: scrambled softmax gather, cat, fuse, fusiondis, output + labels
// ---------------------------------------------------------------------------
__global__ __launch_bounds__(128) void final_kernel(
    const float* __restrict__ x, const float* __restrict__ labels,
    const float* __restrict__ DisM, const float* __restrict__ fuse1,
    const float* __restrict__ biasf, const float* __restrict__ ff,
    const float* __restrict__ bff, const float* __restrict__ Wout,
    const float* __restrict__ biasout, const float* __restrict__ a,
    float* __restrict__ out, int out_size)
{
  int tb = blockIdx.x; int t=tb>>9, b=tb&511;
  __shared__ float wa[10], swA[10], cat[300], xw[17], mix[100];
  int tid = threadIdx.x;
  if (tid==0){
    float d[10], mx=-1e30f;
    #pragma unroll
    for(int i=0;i<10;i++){ d[i]=DisM[i]; mx=fmaxf(mx,d[i]); }
    float s=0.f;
    #pragma unroll
    for(int i=0;i<10;i++){ float e=__expf(d[i]-mx); swA[i]=e; s+=e; }
    float inv = 1.f/s;
    #pragma unroll
    for(int i=0;i<10;i++) swA[i]*=inv;
  }
  if (tid<10){
    int j = b*10+tid;
    int ko = j>>9, bo = j&511;
    wa[tid] = __expf(g_wdyn[(t*512+bo)*10+ko]) / g_den[t*512+bo];
  }
  __syncthreads();
  for (int h=tid; h<300; h+=128){
    float s=0.f;
    #pragma unroll
    for(int k=0;k<10;k++) s = fmaf(g_Con1[(tb*10+k)*300+h], wa[k], s);
    cat[h]=s;
  }
  if (tid<17){
    const float* xp = x + (b*32+t)*280 + (11+tid)*10;
    float s=0.f;
    #pragma unroll
    for(int k=0;k<10;k++) s = fmaf(xp[k], swA[k], s);
    xw[tid]=s;
  }
  __syncthreads();
  float aa = a[0];
  if (tid<100){
    float fu = biasf[tid];
    for(int h=0;h<300;h++) fu = fmaf(cat[h], fuse1[h*100+tid], fu);
    float fd = bff[tid];
    #pragma unroll
    for(int f=0;f<17;f++) fd = fmaf(ff[tid*17+f], xw[f], fd);
    mix[tid] = (aa*fu + (1.f-aa)*fd) * Wout[tid];
  }
  __syncthreads();
  if (tid==0){
    float s = biasout[0];
    for(int o=0;o<100;o++) s += mix[o];
    out[t*512+b] = s;
  }
  if (tid==1 && out_size >= 2*TB){
    out[TB + t*512+b] = labels[b*32+t];
  }
}

// ---------------------------------------------------------------------------
extern "C" void kernel_launch(void* const* d_in, const int* in_sizes, int n_in,
                              void* d_out, int out_size)
{
  const float* x      = (const float*)d_in[0];
  const float* labels = (const float*)d_in[1];
  const float* extras = (const float*)d_in[2];
  const float* DisM   = (const float*)d_in[3];
  const float* AngleM = (const float*)d_in[4];
  const float* Wih    = (const float*)d_in[5];
  const float* b_ih   = (const float*)d_in[6];
  const float* b_hh   = (const float*)d_in[7];
  const float* Wt     = (const float*)d_in[8];
  const float* bt_ih  = (const float*)d_in[9];
  const float* bt_hh  = (const float*)d_in[10];
  const float* wp     = (const float*)d_in[11];
  const float* bp     = (const float*)d_in[12];
  const float* F1     = (const float*)d_in[13];
  const float* b1     = (const float*)d_in[14];
  const float* F2     = (const float*)d_in[15];
  const float* b2     = (const float*)d_in[16];
  const float* ff     = (const float*)d_in[17];
  const float* bff    = (const float*)d_in[18];
  const float* fuse1  = (const float*)d_in[19];
  const float* biasf  = (const float*)d_in[20];
  const float* Wout   = (const float*)d_in[21];
  const float* biasout= (const float*)d_in[22];
  const float* a      = (const float*)d_in[23];
  float* out = (float*)d_out;

  // dyn smem: MODE0 = 2*128*20*4 + 2*16*168*4 = 41984 ; MODE2 = 20480 + 2*16*232*4 = 50176
  cudaFuncSetAttribute((const void*)mma_gemm<0>,
                       cudaFuncAttributeMaxDynamicSharedMemorySize, 51200);
  cudaFuncSetAttribute((const void*)mma_gemm<2>,
                       cudaFuncAttributeMaxDynamicSharedMemorySize, 51200);

  round_weights<<<(180000+255)/256,256>>>(wp, F1);
  cells_kernel<<<dim3(512,10),320>>>(x, Wih, b_ih, b_hh);
  target_kernel<<<(TB*300+255)/256,256>>>(extras, Wt, bt_ih, bt_hh);
  copy_con0<<<1500,256>>>();
  // con1 = relu([Con_t|Con_{t-1}] @ wp^T + bp)  M=158720 (1240), N=300 (2 x BN=160)
  mma_gemm<0><<<dim3(2,1240),256,41984>>>(bp, 300, nullptr, nullptr, nullptr, nullptr);
  // wdyn via fc1 = relu([Con1|ht] @ F1 + b1)    M=163840 (1280), N=200 (1 x BN=224)
  mma_gemm<2><<<dim3(1,1280),256,50176>>>(b1, 200, x, AngleM, F2, b2);
  denom_kernel<<<TB/256, 256>>>();
  final_kernel<<<TB, 128>>>(x, labels, DisM, fuse1, biasf, ff, bff,
                            Wout, biasout, a, out, out_size);
}

// round 7
// speedup vs baseline: 4.3002x; 1.4406x over previous
#include <cuda_runtime.h>
#include <cuda_bf16.h>
#include <cstdint>

// Shapes
#define T_DIM 32
#define B_DIM 512
#define H_DIM 300
#define TB    16384          // T*B
#define NROWS 163840         // TB*10

#define BM 128
#define NCH 19               // ceil(600/32), BK=32

// Scratch (device globals — no allocation)
__device__ __align__(16) __nv_bfloat16 g_Con [NROWS*300]; // cells out [t,b,k,h]
__device__ __align__(16) __nv_bfloat16 g_Con1[NROWS*300]; // con1
__device__ __align__(16) __nv_bfloat16 g_ht  [TB*300];    // htarget
__device__ __align__(16) __nv_bfloat16 g_wpB [300*600];   // wp  [n][k] bf16
__device__ __align__(16) __nv_bfloat16 g_F1B [200*600];   // F1^T [n][k] bf16
__device__ float g_wdyn[NROWS];
__device__ float g_den [TB];

__device__ __forceinline__ float ftanh(float x){
  float r; asm("tanh.approx.f32 %0, %1;" : "=f"(r) : "f"(x)); return r;
}
__device__ __forceinline__ float fsig(float x){
  return fmaf(ftanh(0.5f*x), 0.5f, 0.5f);
}

// ---------------------------------------------------------------------------
// cells (outputs bf16)
// ---------------------------------------------------------------------------
__global__ __launch_bounds__(320) void cells_kernel(
    const float* __restrict__ x, const float* __restrict__ Wih,
    const float* __restrict__ bih, const float* __restrict__ bhh)
{
  int k = blockIdx.y;
  __shared__ float sW[9900];
  __shared__ float sb[900];
  int base = k*13200;
  for (int idx=threadIdx.x; idx<3300; idx+=320){
    sW[idx]      = Wih[base + idx];
    sW[3300+idx] = Wih[base + 6600 + idx];
    sW[6600+idx] = Wih[base + 9900 + idx];
  }
  for (int idx=threadIdx.x; idx<300; idx+=320){
    sb[idx]     = bih[k*1200+idx]     + bhh[k*1200+idx];
    sb[300+idx] = bih[k*1200+600+idx] + bhh[k*1200+600+idx];
    sb[600+idx] = bih[k*1200+900+idx] + bhh[k*1200+900+idx];
  }
  __syncthreads();
  int h = threadIdx.x;
  int tb0 = blockIdx.x*32;
  for (int tb=tb0; tb<tb0+32; tb++){
    int t = tb>>9, b = tb & 511;
    const float* xp = x + ((b*32+t)*28)*10 + k;
    float xs[11];
    #pragma unroll
    for(int i=0;i<11;i++) xs[i] = __ldg(xp + i*10);
    if (h < 300){
      float gi=sb[h], gg=sb[300+h], go=sb[600+h];
      #pragma unroll
      for(int i=0;i<11;i++){
        gi = fmaf(sW[h*11+i],      xs[i], gi);
        gg = fmaf(sW[3300+h*11+i], xs[i], gg);
        go = fmaf(sW[6600+h*11+i], xs[i], go);
      }
      g_Con[(tb*10+k)*300+h] = __float2bfloat16(fsig(go)*ftanh(fsig(gi)*ftanh(gg)));
    }
  }
}

// ---------------------------------------------------------------------------
// target cell (outputs bf16)
// ---------------------------------------------------------------------------
__global__ __launch_bounds__(256) void target_kernel(
    const float* __restrict__ extras, const float* __restrict__ Wt,
    const float* __restrict__ bti, const float* __restrict__ bth)
{
  int idx = blockIdx.x*blockDim.x+threadIdx.x;
  if (idx >= TB*300) return;
  int tb = idx/300, h = idx - tb*300;
  int t = tb>>9, b = tb&511;
  const float* e = extras + (b*32+t)*4;
  float e0=e[0], e1=e[1], e2=e[2], e3=e[3];
  const float* w = Wt + h*4;
  float gi = w[0]*e0+w[1]*e1+w[2]*e2+w[3]*e3 + bti[h]+bth[h];
  w = Wt + (600+h)*4;
  float gg = w[0]*e0+w[1]*e1+w[2]*e2+w[3]*e3 + bti[600+h]+bth[600+h];
  w = Wt + (900+h)*4;
  float go = w[0]*e0+w[1]*e1+w[2]*e2+w[3]*e3 + bti[900+h]+bth[900+h];
  g_ht[idx] = __float2bfloat16(fsig(go)*ftanh(fsig(gi)*ftanh(gg)));
}

// t=0 rows: con1 = con0 (bf16 copy, 1.536M elems = 192000 uint4)
__global__ void copy_con0(){
  int i = blockIdx.x*blockDim.x+threadIdx.x;
  if (i < 192000) ((uint4*)g_Con1)[i] = ((const uint4*)g_Con)[i];
}

// wp [300][600] -> bf16 direct; F1 [600][200] -> transposed bf16 [200][600]
__global__ void round_weights(const float* __restrict__ wp, const float* __restrict__ F1){
  int i = blockIdx.x*blockDim.x+threadIdx.x;
  if (i < 180000) g_wpB[i] = __float2bfloat16(wp[i]);
  if (i < 120000){
    int n = i/600, kk = i - n*600;
    g_F1B[i] = __float2bfloat16(F1[kk*200 + n]);
  }
}

// ---------------------------------------------------------------------------
// bf16 mma.sync m16n8k16 GEMM, 128xBN tile, BK=32, double-buffered, 8 warps.
// MODE 0: con1 = relu([Con_t|Con_{t-1}] @ wp^T + bp)  M=158720, N=300, BN=160
// MODE 2: wdyn from fc1=relu([Con1|ht] @ F1 + b1)     M=163840, N=200, BN=224
// Smem: As [2][128][20 words] ; Bs [2][BN][20 words]  (word = 2 bf16 = k-pair)
// ---------------------------------------------------------------------------
template<int MODE>
__global__ __launch_bounds__(256) void mma_gemm(
    const float* __restrict__ bias, int Ntot,
    const float* __restrict__ x, const float* __restrict__ AngleM,
    const float* __restrict__ F2, const float* __restrict__ b2)
{
  constexpr int BN   = (MODE==0) ? 160 : 224;
  constexpr int NI   = (MODE==0) ? 5   : 7;     // per-warp n tiles of 8
  constexpr int WNW  = BN/4;                    // warp n width
  constexpr int TOTB = BN*4;                    // B uint4 per chunk
  constexpr int BIT  = (TOTB + 255)/256;        // B stage iters (3 / 4)

  extern __shared__ uint32_t smw[];
  uint32_t* AsW = smw;                          // [2][128][20]
  uint32_t* BsW = smw + 2*BM*20;                // [2][BN][20]
  __shared__ float sF2[224];
  __shared__ float sdyn[BM];

  const __nv_bfloat16* Asrc0 = (MODE==0) ? (g_Con + 1536000) : g_Con1;
  const __nv_bfloat16* Asrc1 = (MODE==0) ? g_Con : g_ht;
  const __nv_bfloat16* Bsrc  = (MODE==0) ? g_wpB : g_F1B;

  int tid = threadIdx.x, lane = tid&31, wid = tid>>5;
  int warpM = wid>>2, warpN = wid&3;
  int g = lane>>2, tg = lane&3;
  int m0 = blockIdx.y*BM, n0 = blockIdx.x*BN;

  if (MODE==2){
    if (tid < 224) sF2[tid] = (tid < 200) ? F2[tid] : 0.f;
    if (tid < BM)  sdyn[tid] = 0.f;
  }

  // A staging: 128 rows x 8 uint2 (4 bf16 each) = 1024 -> 4/thread
  int am[4], au[4]; long aoff0[4], aoff1[4];
  #pragma unroll
  for (int j=0;j<4;j++){
    int idx = tid + j*256;
    am[j] = idx>>3; au[j] = idx&7;
    int m = m0 + am[j];
    aoff0[j] = (long)m*300;
    aoff1[j] = (MODE==0) ? (long)m*300 : (long)(m/10)*300;
  }
  // B staging: BN rows x 4 uint4 (8 bf16 each)
  int bn[BIT], bq[BIT];
  #pragma unroll
  for (int j=0;j<BIT;j++){
    int idx = tid + j*256;
    bn[j] = idx>>2; bq[j] = idx&3;
  }

  float acc[4][NI][4];
  #pragma unroll
  for(int i=0;i<4;i++) for(int jn=0;jn<NI;jn++) for(int r=0;r<4;r++) acc[i][jn][r]=0.f;

  uint2 aR[4]; uint4 bR[BIT];
  const uint2 z2 = make_uint2(0,0);
  const uint4 z4c = make_uint4(0,0,0,0);

  auto fetchA = [&](int j, int k0)->uint2{
    int kk = k0 + au[j]*4;                      // element index, mult of 4
    if (kk < 300)      return *(const uint2*)(Asrc0 + aoff0[j] + kk);
    else if (kk < 600) return *(const uint2*)(Asrc1 + aoff1[j] + (kk-300));
    return z2;
  };
  auto fetchB = [&](int j, int k0)->uint4{
    int idx = bn[j]*4 + bq[j];
    int kk = k0 + bq[j]*8;                      // element index, mult of 8
    int n  = n0 + bn[j];
    if (idx < TOTB && kk < 600 && n < Ntot)
      return *(const uint4*)(Bsrc + (long)n*600 + kk);
    return z4c;
  };
  auto stash = [&](int buf){
    #pragma unroll
    for (int j=0;j<4;j++)
      *(uint2*)&AsW[(buf*BM + am[j])*20 + au[j]*2] = aR[j];
    #pragma unroll
    for (int j=0;j<BIT;j++){
      int idx = bn[j]*4 + bq[j];
      if (idx < TOTB)
        *(uint4*)&BsW[(buf*BN + bn[j])*20 + bq[j]*4] = bR[j];
    }
  };

  // prefetch chunk 0
  #pragma unroll
  for (int j=0;j<4;j++)  aR[j] = fetchA(j, 0);
  #pragma unroll
  for (int j=0;j<BIT;j++) bR[j] = fetchB(j, 0);
  stash(0);
  __syncthreads();

  for (int c=0; c<NCH; c++){
    int buf = c & 1;
    if (c+1 < NCH){
      int k0 = (c+1)*32;
      #pragma unroll
      for (int j=0;j<4;j++)  aR[j] = fetchA(j, k0);
      #pragma unroll
      for (int j=0;j<BIT;j++) bR[j] = fetchB(j, k0);
    }
    #pragma unroll
    for (int ks=0; ks<2; ks++){
      int kw = ks*8;
      uint32_t af[4][4];
      #pragma unroll
      for (int mi=0; mi<4; mi++){
        int mr = warpM*64 + mi*16;
        af[mi][0] = AsW[(buf*BM + mr+g  )*20 + kw+tg  ];
        af[mi][1] = AsW[(buf*BM + mr+g+8)*20 + kw+tg  ];
        af[mi][2] = AsW[(buf*BM + mr+g  )*20 + kw+tg+4];
        af[mi][3] = AsW[(buf*BM + mr+g+8)*20 + kw+tg+4];
      }
      uint32_t bfr[NI][2];
      #pragma unroll
      for (int ni=0; ni<NI; ni++){
        int nc = warpN*WNW + ni*8;
        bfr[ni][0] = BsW[(buf*BN + nc+g)*20 + kw+tg  ];
        bfr[ni][1] = BsW[(buf*BN + nc+g)*20 + kw+tg+4];
      }
      #pragma unroll
      for (int mi=0; mi<4; mi++)
        #pragma unroll
        for (int ni=0; ni<NI; ni++){
          asm volatile(
            "mma.sync.aligned.m16n8k16.row.col.f32.bf16.bf16.f32 "
            "{%0,%1,%2,%3}, {%4,%5,%6,%7}, {%8,%9}, {%0,%1,%2,%3};"
            : "+f"(acc[mi][ni][0]), "+f"(acc[mi][ni][1]),
              "+f"(acc[mi][ni][2]), "+f"(acc[mi][ni][3])
            : "r"(af[mi][0]), "r"(af[mi][1]), "r"(af[mi][2]), "r"(af[mi][3]),
              "r"(bfr[ni][0]), "r"(bfr[ni][1]));
        }
    }
    if (c+1 < NCH) stash(buf ^ 1);
    __syncthreads();
  }

  if (MODE==0){
    // epilogue: bias + relu, packed bf16x2 stores to Con1
    __nv_bfloat16* Cptr = g_Con1 + 1536000;
    #pragma unroll
    for (int mi=0; mi<4; mi++){
      #pragma unroll
      for (int ni=0; ni<NI; ni++){
        int row = m0 + warpM*64 + mi*16 + g;
        int col = n0 + warpN*WNW + ni*8 + tg*2;
        if (col < Ntot){
          float b0v = bias[col], b1v = bias[col+1];
          __nv_bfloat162 p0 = __floats2bfloat162_rn(
              fmaxf(acc[mi][ni][0] + b0v, 0.f), fmaxf(acc[mi][ni][1] + b1v, 0.f));
          __nv_bfloat162 p1 = __floats2bfloat162_rn(
              fmaxf(acc[mi][ni][2] + b0v, 0.f), fmaxf(acc[mi][ni][3] + b1v, 0.f));
          *(__nv_bfloat162*)&Cptr[(long)row*300 + col]     = p0;
          *(__nv_bfloat162*)&Cptr[(long)(row+8)*300 + col] = p1;
        }
      }
    }
  } else {
    // fused wdyn: per-row dot of relu(fc1+bias) with F2[:200]
    #pragma unroll
    for (int mi=0; mi<4; mi++){
      float p0 = 0.f, p1 = 0.f;
      #pragma unroll
      for (int ni=0; ni<NI; ni++){
        int col = n0 + warpN*WNW + ni*8 + tg*2;
        if (col < Ntot){
          float b0v = bias[col], b1v = bias[col+1];
          float f20 = sF2[col], f21 = sF2[col+1];
          p0 = fmaf(fmaxf(acc[mi][ni][0] + b0v, 0.f), f20, p0);
          p0 = fmaf(fmaxf(acc[mi][ni][1] + b1v, 0.f), f21, p0);
          p1 = fmaf(fmaxf(acc[mi][ni][2] + b0v, 0.f), f20, p1);
          p1 = fmaf(fmaxf(acc[mi][ni][3] + b1v, 0.f), f21, p1);
        }
      }
      p0 += __shfl_xor_sync(0xffffffffu, p0, 1);
      p0 += __shfl_xor_sync(0xffffffffu, p0, 2);
      p1 += __shfl_xor_sync(0xffffffffu, p1, 1);
      p1 += __shfl_xor_sync(0xffffffffu, p1, 2);
      if (tg == 0){
        int lr = warpM*64 + mi*16 + g;
        atomicAdd(&sdyn[lr], p0);
        atomicAdd(&sdyn[lr+8], p1);
      }
    }
    __syncthreads();
    if (tid < BM){
      int r = m0 + tid;
      int tb = r/10, k = r - tb*10;
      int t = tb>>9, b = tb&511;
      const float* xb = x + (b*32+t)*280;
      float x8  = xb[80+k];
      float ang = fabsf(xb[100+k] - AngleM[k]) * (1.f/360.f);
      float w = sdyn[tid] + x8*F2[200] + ang*F2[201] + b2[0];
      g_wdyn[r] = fmaxf(w, 0.f);
    }
  }
}

__global__ void denom_kernel(){
  int tb = blockIdx.x*blockDim.x+threadIdx.x;
  if (tb >= TB) return;
  float s=0.f;
  #pragma unroll
  for(int k=0;k<10;k++) s += __expf(g_wdyn[tb*10+k]);
  g_den[tb]=s;
}

// ---------------------------------------------------------------------------
// final: scrambled softmax gather, cat, fuse, fusiondis, output + labels
// ---------------------------------------------------------------------------
__global__ __launch_bounds__(128) void final_kernel(
    const float* __restrict__ x, const float* __restrict__ labels,
    const float* __restrict__ DisM, const float* __restrict__ fuse1,
    const float* __restrict__ biasf, const float* __restrict__ ff,
    const float* __restrict__ bff, const float* __restrict__ Wout,
    const float* __restrict__ biasout, const float* __restrict__ a,
    float* __restrict__ out, int out_size)
{
  int tb = blockIdx.x; int t=tb>>9, b=tb&511;
  __shared__ float wa[10], swA[10], cat[300], xw[17], mix[100];
  int tid = threadIdx.x;
  if (tid==0){
    float d[10], mx=-1e30f;
    #pragma unroll
    for(int i=0;i<10;i++){ d[i]=DisM[i]; mx=fmaxf(mx,d[i]); }
    float s=0.f;
    #pragma unroll
    for(int i=0;i<10;i++){ float e=__expf(d[i]-mx); swA[i]=e; s+=e; }
    float inv = 1.f/s;
    #pragma unroll
    for(int i=0;i<10;i++) swA[i]*=inv;
  }
  if (tid<10){
    int j = b*10+tid;
    int ko = j>>9, bo = j&511;
    wa[tid] = __expf(g_wdyn[(t*512+bo)*10+ko]) / g_den[t*512+bo];
  }
  __syncthreads();
  for (int h=tid; h<300; h+=128){
    float s=0.f;
    #pragma unroll
    for(int k=0;k<10;k++)
      s = fmaf(__bfloat162float(g_Con1[(long)(tb*10+k)*300+h]), wa[k], s);
    cat[h]=s;
  }
  if (tid<17){
    const float* xp = x + (b*32+t)*280 + (11+tid)*10;
    float s=0.f;
    #pragma unroll
    for(int k=0;k<10;k++) s = fmaf(xp[k], swA[k], s);
    xw[tid]=s;
  }
  __syncthreads();
  float aa = a[0];
  if (tid<100){
    float fu = biasf[tid];
    for(int h=0;h<300;h++) fu = fmaf(cat[h], fuse1[h*100+tid], fu);
    float fd = bff[tid];
    #pragma unroll
    for(int f=0;f<17;f++) fd = fmaf(ff[tid*17+f], xw[f], fd);
    mix[tid] = (aa*fu + (1.f-aa)*fd) * Wout[tid];
  }
  __syncthreads();
  if (tid==0){
    float s = biasout[0];
    for(int o=0;o<100;o++) s += mix[o];
    out[t*512+b] = s;
  }
  if (tid==1 && out_size >= 2*TB){
    out[TB + t*512+b] = labels[b*32+t];
  }
}

// ---------------------------------------------------------------------------
extern "C" void kernel_launch(void* const* d_in, const int* in_sizes, int n_in,
                              void* d_out, int out_size)
{
  const float* x      = (const float*)d_in[0];
  const float* labels = (const float*)d_in[1];
  const float* extras = (const float*)d_in[2];
  const float* DisM   = (const float*)d_in[3];
  const float* AngleM = (const float*)d_in[4];
  const float* Wih    = (const float*)d_in[5];
  const float* b_ih   = (const float*)d_in[6];
  const float* b_hh   = (const float*)d_in[7];
  const float* Wt     = (const float*)d_in[8];
  const float* bt_ih  = (const float*)d_in[9];
  const float* bt_hh  = (const float*)d_in[10];
  const float* wp     = (const float*)d_in[11];
  const float* bp     = (const float*)d_in[12];
  const float* F1     = (const float*)d_in[13];
  const float* b1     = (const float*)d_in[14];
  const float* F2     = (const float*)d_in[15];
  const float* b2     = (const float*)d_in[16];
  const float* ff     = (const float*)d_in[17];
  const float* bff    = (const float*)d_in[18];
  const float* fuse1  = (const float*)d_in[19];
  const float* biasf  = (const float*)d_in[20];
  const float* Wout   = (const float*)d_in[21];
  const float* biasout= (const float*)d_in[22];
  const float* a      = (const float*)d_in[23];
  float* out = (float*)d_out;

  // dyn smem (bytes): MODE0 = (2*128*20 + 2*160*20)*4 = 46080
  //                   MODE2 = (2*128*20 + 2*224*20)*4 = 56320
  cudaFuncSetAttribute((const void*)mma_gemm<0>,
                       cudaFuncAttributeMaxDynamicSharedMemorySize, 57344);
  cudaFuncSetAttribute((const void*)mma_gemm<2>,
                       cudaFuncAttributeMaxDynamicSharedMemorySize, 57344);

  round_weights<<<(180000+255)/256,256>>>(wp, F1);
  cells_kernel<<<dim3(512,10),320>>>(x, Wih, b_ih, b_hh);
  target_kernel<<<(TB*300+255)/256,256>>>(extras, Wt, bt_ih, bt_hh);
  copy_con0<<<750,256>>>();
  // con1 = relu([Con_t|Con_{t-1}] @ wp^T + bp)  M=158720 (1240), N=300 (2 x BN=160)
  mma_gemm<0><<<dim3(2,1240),256,46080>>>(bp, 300, nullptr, nullptr, nullptr, nullptr);
  // wdyn via fc1 = relu([Con1|ht] @ F1 + b1)    M=163840 (1280), N=200 (1 x BN=224)
  mma_gemm<2><<<dim3(1,1280),256,56320>>>(b1, 200, x, AngleM, F2, b2);
  denom_kernel<<<TB/256, 256>>>();
  final_kernel<<<TB, 128>>>(x, labels, DisM, fuse1, biasf, ff, bff,
                            Wout, biasout, a, out, out_size);
}

// round 11
// speedup vs baseline: 4.5801x; 1.0651x over previous
#include <cuda_runtime.h>
#include <cuda_bf16.h>
#include <cstdint>

// Shapes
#define T_DIM 32
#define B_DIM 512
#define H_DIM 300
#define TB    16384          // T*B
#define NROWS 163840         // TB*10

#define BM 128

// Scratch (device globals — no allocation)
__device__ __align__(16) __nv_bfloat16 g_Con [NROWS*300]; // cells out [t,b,k,h]
__device__ __align__(16) __nv_bfloat16 g_Con1[NROWS*300]; // con1
__device__ __align__(16) __nv_bfloat16 g_ht  [TB*300];    // htarget
__device__ __align__(16) __nv_bfloat16 g_wpB [300*600+16];// wp  [n][k] bf16
__device__ __align__(16) __nv_bfloat16 g_F1Ba[200*304];   // F1^T[:,0:300]  stride 304
__device__ __align__(16) __nv_bfloat16 g_F1Bb[200*304];   // F1^T[:,300:600] stride 304
__device__ float g_htF [TB*200];     // ht @ F1[300:600] + b1 (fp32)
__device__ float g_wdyn[NROWS];
__device__ float g_den [TB];

__device__ __forceinline__ float ftanh(float x){
  float r; asm("tanh.approx.f32 %0, %1;" : "=f"(r) : "f"(x)); return r;
}
__device__ __forceinline__ float fsig(float x){
  return fmaf(ftanh(0.5f*x), 0.5f, 0.5f);
}

// ---------------------------------------------------------------------------
// cells: smem-staged weights copied once to registers, then pure FFMA loop
// ---------------------------------------------------------------------------
__global__ __launch_bounds__(320) void cells_kernel(
    const float* __restrict__ x, const float* __restrict__ Wih,
    const float* __restrict__ bih, const float* __restrict__ bhh)
{
  int k = blockIdx.y;
  __shared__ float sW[9900];
  int base = k*13200;
  for (int idx=threadIdx.x; idx<3300; idx+=320){
    sW[idx]      = Wih[base + idx];          // gate i rows 0..299
    sW[3300+idx] = Wih[base + 6600 + idx];   // gate g rows 600..899
    sW[6600+idx] = Wih[base + 9900 + idx];   // gate o rows 900..1199
  }
  __syncthreads();
  int h = threadIdx.x;
  float wi[11], wg[11], wo[11], bi=0.f, bg=0.f, bo=0.f;
  if (h < 300){
    #pragma unroll
    for (int i=0;i<11;i++){
      wi[i] = sW[h*11+i];
      wg[i] = sW[3300+h*11+i];
      wo[i] = sW[6600+h*11+i];
    }
    bi = bih[k*1200+h]     + bhh[k*1200+h];
    bg = bih[k*1200+600+h] + bhh[k*1200+600+h];
    bo = bih[k*1200+900+h] + bhh[k*1200+900+h];
  }
  int tb0 = blockIdx.x*32;
  for (int tb=tb0; tb<tb0+32; tb++){
    int t = tb>>9, b = tb & 511;
    const float* xp = x + ((b*32+t)*28)*10 + k;
    float xs[11];
    #pragma unroll
    for(int i=0;i<11;i++) xs[i] = __ldg(xp + i*10);
    if (h < 300){
      float gi=bi, gg=bg, go=bo;
      #pragma unroll
      for(int i=0;i<11;i++){
        gi = fmaf(wi[i], xs[i], gi);
        gg = fmaf(wg[i], xs[i], gg);
        go = fmaf(wo[i], xs[i], go);
      }
      g_Con[(tb*10+k)*300+h] = __float2bfloat16(fsig(go)*ftanh(fsig(gi)*ftanh(gg)));
    }
  }
}

// ---------------------------------------------------------------------------
// target cell (outputs bf16)
// ---------------------------------------------------------------------------
__global__ __launch_bounds__(256) void target_kernel(
    const float* __restrict__ extras, const float* __restrict__ Wt,
    const float* __restrict__ bti, const float* __restrict__ bth)
{
  int idx = blockIdx.x*blockDim.x+threadIdx.x;
  if (idx >= TB*300) return;
  int tb = idx/300, h = idx - tb*300;
  int t = tb>>9, b = tb&511;
  const float* e = extras + (b*32+t)*4;
  float e0=e[0], e1=e[1], e2=e[2], e3=e[3];
  const float* w = Wt + h*4;
  float gi = w[0]*e0+w[1]*e1+w[2]*e2+w[3]*e3 + bti[h]+bth[h];
  w = Wt + (600+h)*4;
  float gg = w[0]*e0+w[1]*e1+w[2]*e2+w[3]*e3 + bti[600+h]+bth[600+h];
  w = Wt + (900+h)*4;
  float go = w[0]*e0+w[1]*e1+w[2]*e2+w[3]*e3 + bti[900+h]+bth[900+h];
  g_ht[idx] = __float2bfloat16(fsig(go)*ftanh(fsig(gi)*ftanh(gg)));
}

// t=0 rows: con1 = con0 (bf16 copy)
__global__ void copy_con0(){
  int i = blockIdx.x*blockDim.x+threadIdx.x;
  if (i < 192000) ((uint4*)g_Con1)[i] = ((const uint4*)g_Con)[i];
}

// wp [300][600] -> bf16; F1 [600][200] -> two transposed halves, stride 304
__global__ void round_weights(const float* __restrict__ wp, const float* __restrict__ F1){
  int i = blockIdx.x*blockDim.x+threadIdx.x;
  if (i < 180000) g_wpB[i] = __float2bfloat16(wp[i]);
  if (i < 60800){
    int n = i/304, kk = i - n*304;
    g_F1Ba[i] = (kk<300) ? __float2bfloat16(F1[kk*200 + n])       : __nv_bfloat16(0.f);
    g_F1Bb[i] = (kk<300) ? __float2bfloat16(F1[(300+kk)*200 + n]) : __nv_bfloat16(0.f);
  }
}

// ---------------------------------------------------------------------------
// bf16 mma.sync m16n8k16 GEMM, 128xBN tile, BK=32, double-buffered, 8 warps.
// MODE 0: con1 = relu([Con_t|Con_{t-1}] @ wp^T + bp)  M=158720, N=300, K=600, BN=160
// MODE 1: htF  = ht @ F1[300:600]^T + b1 (fp32)       M=16384,  N=200, K=300, BN=224
// MODE 2: wdyn from fc1=relu(Con1@F1[0:300]^T + htF)  M=163840, N=200, K=300, BN=224
// ---------------------------------------------------------------------------
template<int MODE>
__global__ __launch_bounds__(256) void mma_gemm(
    const float* __restrict__ bias,
    const float* __restrict__ x, const float* __restrict__ AngleM,
    const float* __restrict__ F2, const float* __restrict__ b2)
{
  constexpr int BN   = (MODE==0) ? 160 : 224;
  constexpr int NI   = (MODE==0) ? 5   : 7;
  constexpr int WNW  = BN/4;
  constexpr int TOTB = BN*4;
  constexpr int BIT  = (TOTB + 255)/256;
  constexpr int NCHv = (MODE==0) ? 19 : 10;
  constexpr int KLEN = (MODE==0) ? 600 : 300;
  constexpr int LDB  = (MODE==0) ? 600 : 304;
  const int Ntot = (MODE==0) ? 300 : 200;

  extern __shared__ uint32_t smw[];
  uint32_t* AsW = smw;                          // [2][128][20]
  uint32_t* BsW = smw + 2*BM*20;                // [2][BN][20]
  __shared__ float sF2[224];
  __shared__ float sdyn[BM];

  const __nv_bfloat16* Bsrc = (MODE==0) ? g_wpB : ((MODE==1) ? g_F1Bb : g_F1Ba);

  int tid = threadIdx.x, lane = tid&31, wid = tid>>5;
  int warpM = wid>>2, warpN = wid&3;
  int g = lane>>2, tg = lane&3;
  int m0 = blockIdx.y*BM, n0 = blockIdx.x*BN;

  if (MODE==2){
    if (tid < 224) sF2[tid] = (tid < 200) ? F2[tid] : 0.f;
    if (tid < BM)  sdyn[tid] = 0.f;
  }

  int am[4], au[4]; long aoff0[4];
  #pragma unroll
  for (int j=0;j<4;j++){
    int idx = tid + j*256;
    am[j] = idx>>3; au[j] = idx&7;
    aoff0[j] = (long)(m0 + am[j])*300;
  }
  int bn[BIT], bq[BIT];
  #pragma unroll
  for (int j=0;j<BIT;j++){
    int idx = tid + j*256;
    bn[j] = idx>>2; bq[j] = idx&3;
  }

  float acc[4][NI][4];
  #pragma unroll
  for(int i=0;i<4;i++) for(int jn=0;jn<NI;jn++) for(int r=0;r<4;r++) acc[i][jn][r]=0.f;

  uint2 aR[4]; uint4 bR[BIT];
  const uint2 z2 = make_uint2(0,0);
  const uint4 z4c = make_uint4(0,0,0,0);

  auto fetchA = [&](int j, int k0)->uint2{
    int kk = k0 + au[j]*4;
    if (MODE==0){
      if (kk < 300)      return *(const uint2*)(g_Con + 1536000 + aoff0[j] + kk);
      else if (kk < 600) return *(const uint2*)(g_Con + aoff0[j] + (kk-300));
      return z2;
    } else if (MODE==1){
      if (kk < 300) return *(const uint2*)(g_ht + aoff0[j] + kk);
      return z2;
    } else {
      if (kk < 300) return *(const uint2*)(g_Con1 + aoff0[j] + kk);
      return z2;
    }
  };
  auto fetchB = [&](int j, int k0)->uint4{
    int idx = bn[j]*4 + bq[j];
    int kk = k0 + bq[j]*8;
    int n  = n0 + bn[j];
    if (idx < TOTB && kk < KLEN && n < Ntot)
      return *(const uint4*)(Bsrc + (long)n*LDB + kk);
    return z4c;
  };
  auto stash = [&](int buf){
    #pragma unroll
    for (int j=0;j<4;j++)
      *(uint2*)&AsW[(buf*BM + am[j])*20 + au[j]*2] = aR[j];
    #pragma unroll
    for (int j=0;j<BIT;j++){
      int idx = bn[j]*4 + bq[j];
      if (idx < TOTB)
        *(uint4*)&BsW[(buf*BN + bn[j])*20 + bq[j]*4] = bR[j];
    }
  };

  #pragma unroll
  for (int j=0;j<4;j++)  aR[j] = fetchA(j, 0);
  #pragma unroll
  for (int j=0;j<BIT;j++) bR[j] = fetchB(j, 0);
  stash(0);
  __syncthreads();

  for (int c=0; c<NCHv; c++){
    int buf = c & 1;
    if (c+1 < NCHv){
      int k0 = (c+1)*32;
      #pragma unroll
      for (int j=0;j<4;j++)  aR[j] = fetchA(j, k0);
      #pragma unroll
      for (int j=0;j<BIT;j++) bR[j] = fetchB(j, k0);
    }
    #pragma unroll
    for (int ks=0; ks<2; ks++){
      int kw = ks*8;
      uint32_t af[4][4];
      #pragma unroll
      for (int mi=0; mi<4; mi++){
        int mr = warpM*64 + mi*16;
        af[mi][0] = AsW[(buf*BM + mr+g  )*20 + kw+tg  ];
        af[mi][1] = AsW[(buf*BM + mr+g+8)*20 + kw+tg  ];
        af[mi][2] = AsW[(buf*BM + mr+g  )*20 + kw+tg+4];
        af[mi][3] = AsW[(buf*BM + mr+g+8)*20 + kw+tg+4];
      }
      uint32_t bfr[NI][2];
      #pragma unroll
      for (int ni=0; ni<NI; ni++){
        int nc = warpN*WNW + ni*8;
        bfr[ni][0] = BsW[(buf*BN + nc+g)*20 + kw+tg  ];
        bfr[ni][1] = BsW[(buf*BN + nc+g)*20 + kw+tg+4];
      }
      #pragma unroll
      for (int mi=0; mi<4; mi++)
        #pragma unroll
        for (int ni=0; ni<NI; ni++){
          asm volatile(
            "mma.sync.aligned.m16n8k16.row.col.f32.bf16.bf16.f32 "
            "{%0,%1,%2,%3}, {%4,%5,%6,%7}, {%8,%9}, {%0,%1,%2,%3};"
            : "+f"(acc[mi][ni][0]), "+f"(acc[mi][ni][1]),
              "+f"(acc[mi][ni][2]), "+f"(acc[mi][ni][3])
            : "r"(af[mi][0]), "r"(af[mi][1]), "r"(af[mi][2]), "r"(af[mi][3]),
              "r"(bfr[ni][0]), "r"(bfr[ni][1]));
        }
    }
    if (c+1 < NCHv) stash(buf ^ 1);
    __syncthreads();
  }

  if (MODE==0){
    __nv_bfloat16* Cptr = g_Con1 + 1536000;
    #pragma unroll
    for (int mi=0; mi<4; mi++){
      #pragma unroll
      for (int ni=0; ni<NI; ni++){
        int row = m0 + warpM*64 + mi*16 + g;
        int col = n0 + warpN*WNW + ni*8 + tg*2;
        if (col < Ntot){
          float b0v = bias[col], b1v = bias[col+1];
          __nv_bfloat162 p0 = __floats2bfloat162_rn(
              fmaxf(acc[mi][ni][0] + b0v, 0.f), fmaxf(acc[mi][ni][1] + b1v, 0.f));
          __nv_bfloat162 p1 = __floats2bfloat162_rn(
              fmaxf(acc[mi][ni][2] + b0v, 0.f), fmaxf(acc[mi][ni][3] + b1v, 0.f));
          *(__nv_bfloat162*)&Cptr[(long)row*300 + col]     = p0;
          *(__nv_bfloat162*)&Cptr[(long)(row+8)*300 + col] = p1;
        }
      }
    }
  } else if (MODE==1){
    #pragma unroll
    for (int mi=0; mi<4; mi++){
      #pragma unroll
      for (int ni=0; ni<NI; ni++){
        int row = m0 + warpM*64 + mi*16 + g;
        int col = n0 + warpN*WNW + ni*8 + tg*2;
        if (col < 200){
          float b0v = bias[col], b1v = bias[col+1];
          *(float2*)&g_htF[(long)row*200 + col] =
              make_float2(acc[mi][ni][0] + b0v, acc[mi][ni][1] + b1v);
          *(float2*)&g_htF[(long)(row+8)*200 + col] =
              make_float2(acc[mi][ni][2] + b0v, acc[mi][ni][3] + b1v);
        }
      }
    }
  } else {
    // fused wdyn: fc1 = relu(acc + htF[row/10]); dot with F2[:200]
    #pragma unroll
    for (int mi=0; mi<4; mi++){
      int row  = m0 + warpM*64 + mi*16 + g;
      long hb0 = (long)(row/10)*200;
      long hb1 = (long)((row+8)/10)*200;
      float p0 = 0.f, p1 = 0.f;
      #pragma unroll
      for (int ni=0; ni<NI; ni++){
        int col = n0 + warpN*WNW + ni*8 + tg*2;
        if (col < 200){
          float h00 = g_htF[hb0+col], h01 = g_htF[hb0+col+1];
          float h10 = g_htF[hb1+col], h11 = g_htF[hb1+col+1];
          float f20 = sF2[col], f21 = sF2[col+1];
          p0 = fmaf(fmaxf(acc[mi][ni][0] + h00, 0.f), f20, p0);
          p0 = fmaf(fmaxf(acc[mi][ni][1] + h01, 0.f), f21, p0);
          p1 = fmaf(fmaxf(acc[mi][ni][2] + h10, 0.f), f20, p1);
          p1 = fmaf(fmaxf(acc[mi][ni][3] + h11, 0.f), f21, p1);
        }
      }
      p0 += __shfl_xor_sync(0xffffffffu, p0, 1);
      p0 += __shfl_xor_sync(0xffffffffu, p0, 2);
      p1 += __shfl_xor_sync(0xffffffffu, p1, 1);
      p1 += __shfl_xor_sync(0xffffffffu, p1, 2);
      if (tg == 0){
        int lr = warpM*64 + mi*16 + g;
        atomicAdd(&sdyn[lr], p0);
        atomicAdd(&sdyn[lr+8], p1);
      }
    }
    __syncthreads();
    if (tid < BM){
      int r = m0 + tid;
      int tb = r/10, k = r - tb*10;
      int t = tb>>9, b = tb&511;
      const float* xb = x + (b*32+t)*280;
      float x8  = xb[80+k];
      float ang = fabsf(xb[100+k] - AngleM[k]) * (1.f/360.f);
      float w = sdyn[tid] + x8*F2[200] + ang*F2[201] + b2[0];
      g_wdyn[r] = fmaxf(w, 0.f);
    }
  }
}

__global__ void denom_kernel(){
  int tb = blockIdx.x*blockDim.x+threadIdx.x;
  if (tb >= TB) return;
  float s=0.f;
  #pragma unroll
  for(int k=0;k<10;k++) s += __expf(g_wdyn[tb*10+k]);
  g_den[tb]=s;
}

// ---------------------------------------------------------------------------
// final v2: 8 tb per block. Phase 1: wa gather + cat (per warp). Phase 2:
// 200 threads x 4 output cols each (float4 fuse1), fd from ff, reduce.
// ---------------------------------------------------------------------------
__global__ __launch_bounds__(256) void final2_kernel(
    const float* __restrict__ x, const float* __restrict__ labels,
    const float* __restrict__ DisM, const float* __restrict__ fuse1,
    const float* __restrict__ biasf, const float* __restrict__ ff,
    const float* __restrict__ bff, const float* __restrict__ Wout,
    const float* __restrict__ biasout, const float* __restrict__ a,
    float* __restrict__ out, int out_size)
{
  __shared__ float sA[10];
  __shared__ float scat[8][304];
  __shared__ float sxw[8][17];
  __shared__ float smix[8][25];
  int tid = threadIdx.x, w = tid>>5, lane = tid&31;
  int tb = blockIdx.x*8 + w; int t = tb>>9, b = tb&511;

  if (tid==0){
    float d[10], mx=-1e30f;
    #pragma unroll
    for(int i=0;i<10;i++){ d[i]=DisM[i]; mx=fmaxf(mx,d[i]); }
    float s=0.f;
    #pragma unroll
    for(int i=0;i<10;i++){ float e=__expf(d[i]-mx); sA[i]=e; s+=e; }
    float inv = 1.f/s;
    #pragma unroll
    for(int i=0;i<10;i++) sA[i]*=inv;
  }
  __syncthreads();

  float wa_l = 0.f;
  if (lane<10){
    int j = b*10+lane;
    int ko = j>>9, bo = j&511;
    wa_l = __expf(g_wdyn[(t*512+bo)*10+ko]) / g_den[t*512+bo];
  }
  float wa[10];
  #pragma unroll
  for (int q=0;q<10;q++) wa[q] = __shfl_sync(0xffffffffu, wa_l, q);

  for (int h=lane; h<304; h+=32){
    float s=0.f;
    if (h<300){
      #pragma unroll
      for(int q=0;q<10;q++)
        s = fmaf(__bfloat162float(g_Con1[(long)(tb*10+q)*300+h]), wa[q], s);
    }
    scat[w][h]=s;
  }
  if (lane<17){
    const float* xp = x + (b*32+t)*280 + (11+lane)*10;
    float s=0.f;
    #pragma unroll
    for(int q=0;q<10;q++) s = fmaf(xp[q], sA[q], s);
    sxw[w][lane]=s;
  }
  __syncthreads();

  float aa = a[0];
  if (tid < 200){
    int w2 = tid/25, og = tid - (tid/25)*25, o0 = og*4;
    float4 fu = make_float4(biasf[o0], biasf[o0+1], biasf[o0+2], biasf[o0+3]);
    const float* sc = scat[w2];
    #pragma unroll 4
    for (int h=0; h<300; h++){
      float s = sc[h];
      float4 f4 = *(const float4*)&fuse1[h*100 + o0];
      fu.x = fmaf(s, f4.x, fu.x);
      fu.y = fmaf(s, f4.y, fu.y);
      fu.z = fmaf(s, f4.z, fu.z);
      fu.w = fmaf(s, f4.w, fu.w);
    }
    float fuv[4] = {fu.x, fu.y, fu.z, fu.w};
    float part = 0.f;
    #pragma unroll
    for (int jo=0;jo<4;jo++){
      int o = o0+jo;
      float fd = bff[o];
      #pragma unroll
      for (int f=0;f<17;f++) fd = fmaf(ff[o*17+f], sxw[w2][f], fd);
      part += (aa*fuv[jo] + (1.f-aa)*fd) * Wout[o];
    }
    smix[w2][og] = part;
  }
  __syncthreads();
  if (tid < 8){
    int tb2 = blockIdx.x*8 + tid; int t2 = tb2>>9, b2 = tb2&511;
    float s = biasout[0];
    #pragma unroll
    for (int og=0; og<25; og++) s += smix[tid][og];
    out[t2*512+b2] = s;
    if (out_size >= 2*TB) out[TB + t2*512+b2] = labels[b2*32+t2];
  }
}

// ---------------------------------------------------------------------------
extern "C" void kernel_launch(void* const* d_in, const int* in_sizes, int n_in,
                              void* d_out, int out_size)
{
  const float* x      = (const float*)d_in[0];
  const float* labels = (const float*)d_in[1];
  const float* extras = (const float*)d_in[2];
  const float* DisM   = (const float*)d_in[3];
  const float* AngleM = (const float*)d_in[4];
  const float* Wih    = (const float*)d_in[5];
  const float* b_ih   = (const float*)d_in[6];
  const float* b_hh   = (const float*)d_in[7];
  const float* Wt     = (const float*)d_in[8];
  const float* bt_ih  = (const float*)d_in[9];
  const float* bt_hh  = (const float*)d_in[10];
  const float* wp     = (const float*)d_in[11];
  const float* bp     = (const float*)d_in[12];
  const float* F1     = (const float*)d_in[13];
  const float* b1     = (const float*)d_in[14];
  const float* F2     = (const float*)d_in[15];
  const float* b2     = (const float*)d_in[16];
  const float* ff     = (const float*)d_in[17];
  const float* bff    = (const float*)d_in[18];
  const float* fuse1  = (const float*)d_in[19];
  const float* biasf  = (const float*)d_in[20];
  const float* Wout   = (const float*)d_in[21];
  const float* biasout= (const float*)d_in[22];
  const float* a      = (const float*)d_in[23];
  float* out = (float*)d_out;

  // dyn smem (bytes): MODE0 = (2*128*20 + 2*160*20)*4 = 46080
  //                   MODE1/2 = (2*128*20 + 2*224*20)*4 = 56320
  cudaFuncSetAttribute((const void*)mma_gemm<0>,
                       cudaFuncAttributeMaxDynamicSharedMemorySize, 57344);
  cudaFuncSetAttribute((const void*)mma_gemm<1>,
                       cudaFuncAttributeMaxDynamicSharedMemorySize, 57344);
  cudaFuncSetAttribute((const void*)mma_gemm<2>,
                       cudaFuncAttributeMaxDynamicSharedMemorySize, 57344);

  round_weights<<<(180000+255)/256,256>>>(wp, F1);
  cells_kernel<<<dim3(512,10),320>>>(x, Wih, b_ih, b_hh);
  target_kernel<<<(TB*300+255)/256,256>>>(extras, Wt, bt_ih, bt_hh);
  copy_con0<<<750,256>>>();
  // con1 = relu([Con_t|Con_{t-1}] @ wp^T + bp)  M=158720 (1240), N=300 (2 x 160)
  mma_gemm<0><<<dim3(2,1240),256,46080>>>(bp, nullptr, nullptr, nullptr, nullptr);
  // htF = ht @ F1[300:600]^T + b1               M=16384 (128), N=200 (1 x 224)
  mma_gemm<1><<<dim3(1,128),256,56320>>>(b1, nullptr, nullptr, nullptr, nullptr);
  // wdyn via fc1 = relu(Con1 @ F1[0:300]^T + htF)  M=163840 (1280)
  mma_gemm<2><<<dim3(1,1280),256,56320>>>(nullptr, x, AngleM, F2, b2);
  denom_kernel<<<TB/256, 256>>>();
  final2_kernel<<<TB/8, 256>>>(x, labels, DisM, fuse1, biasf, ff, bff,
                               Wout, biasout, a, out, out_size);
}

// round 12
// speedup vs baseline: 4.7935x; 1.0466x over previous
#include <cuda_runtime.h>
#include <cuda_bf16.h>
#include <cstdint>

// Shapes
#define T_DIM 32
#define B_DIM 512
#define H_DIM 300
#define TB    16384          // T*B
#define NROWS 163840         // TB*10

#define BM 128

// Scratch (device globals — no allocation)
__device__ __align__(16) __nv_bfloat16 g_Con [NROWS*300]; // cells out [t,b,k,h]
__device__ __align__(16) __nv_bfloat16 g_Con1[NROWS*300]; // con1
__device__ __align__(16) __nv_bfloat16 g_ht  [TB*300];    // htarget
__device__ __align__(16) __nv_bfloat16 g_wpB [300*600+16];// wp  [n][k] bf16
__device__ __align__(16) __nv_bfloat16 g_F1Ba[200*304];   // F1^T[:,0:300]  stride 304
__device__ __align__(16) __nv_bfloat16 g_F1Bb[200*304];   // F1^T[:,300:600] stride 304
__device__ float g_htF [TB*200];     // ht @ F1[300:600] + b1 (fp32)
__device__ float g_wdyn[NROWS];
__device__ float g_den [TB];

__device__ __forceinline__ float ftanh(float x){
  float r; asm("tanh.approx.f32 %0, %1;" : "=f"(r) : "f"(x)); return r;
}
__device__ __forceinline__ float fsig(float x){
  return fmaf(ftanh(0.5f*x), 0.5f, 0.5f);
}
__device__ __forceinline__ void ldsm_x4(uint32_t& r0,uint32_t& r1,uint32_t& r2,uint32_t& r3,
                                        uint32_t saddr){
  asm volatile("ldmatrix.sync.aligned.m8n8.x4.shared.b16 {%0,%1,%2,%3}, [%4];"
               : "=r"(r0),"=r"(r1),"=r"(r2),"=r"(r3) : "r"(saddr));
}
__device__ __forceinline__ void ldsm_x2(uint32_t& r0,uint32_t& r1, uint32_t saddr){
  asm volatile("ldmatrix.sync.aligned.m8n8.x2.shared.b16 {%0,%1}, [%2];"
               : "=r"(r0),"=r"(r1) : "r"(saddr));
}

// ---------------------------------------------------------------------------
// cells: smem-staged weights copied once to registers, then pure FFMA loop
// ---------------------------------------------------------------------------
__global__ __launch_bounds__(320) void cells_kernel(
    const float* __restrict__ x, const float* __restrict__ Wih,
    const float* __restrict__ bih, const float* __restrict__ bhh)
{
  int k = blockIdx.y;
  __shared__ float sW[9900];
  int base = k*13200;
  for (int idx=threadIdx.x; idx<3300; idx+=320){
    sW[idx]      = Wih[base + idx];          // gate i rows 0..299
    sW[3300+idx] = Wih[base + 6600 + idx];   // gate g rows 600..899
    sW[6600+idx] = Wih[base + 9900 + idx];   // gate o rows 900..1199
  }
  __syncthreads();
  int h = threadIdx.x;
  float wi[11], wg[11], wo[11], bi=0.f, bg=0.f, bo=0.f;
  if (h < 300){
    #pragma unroll
    for (int i=0;i<11;i++){
      wi[i] = sW[h*11+i];
      wg[i] = sW[3300+h*11+i];
      wo[i] = sW[6600+h*11+i];
    }
    bi = bih[k*1200+h]     + bhh[k*1200+h];
    bg = bih[k*1200+600+h] + bhh[k*1200+600+h];
    bo = bih[k*1200+900+h] + bhh[k*1200+900+h];
  }
  int tb0 = blockIdx.x*32;
  for (int tb=tb0; tb<tb0+32; tb++){
    int t = tb>>9, b = tb & 511;
    const float* xp = x + ((b*32+t)*28)*10 + k;
    float xs[11];
    #pragma unroll
    for(int i=0;i<11;i++) xs[i] = __ldg(xp + i*10);
    if (h < 300){
      float gi=bi, gg=bg, go=bo;
      #pragma unroll
      for(int i=0;i<11;i++){
        gi = fmaf(wi[i], xs[i], gi);
        gg = fmaf(wg[i], xs[i], gg);
        go = fmaf(wo[i], xs[i], go);
      }
      g_Con[(tb*10+k)*300+h] = __float2bfloat16(fsig(go)*ftanh(fsig(gi)*ftanh(gg)));
    }
  }
}

// ---------------------------------------------------------------------------
// target cell (outputs bf16)
// ---------------------------------------------------------------------------
__global__ __launch_bounds__(256) void target_kernel(
    const float* __restrict__ extras, const float* __restrict__ Wt,
    const float* __restrict__ bti, const float* __restrict__ bth)
{
  int idx = blockIdx.x*blockDim.x+threadIdx.x;
  if (idx >= TB*300) return;
  int tb = idx/300, h = idx - tb*300;
  int t = tb>>9, b = tb&511;
  const float* e = extras + (b*32+t)*4;
  float e0=e[0], e1=e[1], e2=e[2], e3=e[3];
  const float* w = Wt + h*4;
  float gi = w[0]*e0+w[1]*e1+w[2]*e2+w[3]*e3 + bti[h]+bth[h];
  w = Wt + (600+h)*4;
  float gg = w[0]*e0+w[1]*e1+w[2]*e2+w[3]*e3 + bti[600+h]+bth[600+h];
  w = Wt + (900+h)*4;
  float go = w[0]*e0+w[1]*e1+w[2]*e2+w[3]*e3 + bti[900+h]+bth[900+h];
  g_ht[idx] = __float2bfloat16(fsig(go)*ftanh(fsig(gi)*ftanh(gg)));
}

// t=0 rows: con1 = con0 (bf16 copy)
__global__ void copy_con0(){
  int i = blockIdx.x*blockDim.x+threadIdx.x;
  if (i < 192000) ((uint4*)g_Con1)[i] = ((const uint4*)g_Con)[i];
}

// wp [300][600] -> bf16; F1 [600][200] -> two transposed halves, stride 304
__global__ void round_weights(const float* __restrict__ wp, const float* __restrict__ F1){
  int i = blockIdx.x*blockDim.x+threadIdx.x;
  if (i < 180000) g_wpB[i] = __float2bfloat16(wp[i]);
  if (i < 60800){
    int n = i/304, kk = i - n*304;
    g_F1Ba[i] = (kk<300) ? __float2bfloat16(F1[kk*200 + n])       : __nv_bfloat16(0.f);
    g_F1Bb[i] = (kk<300) ? __float2bfloat16(F1[(300+kk)*200 + n]) : __nv_bfloat16(0.f);
  }
}

// ---------------------------------------------------------------------------
// bf16 mma.sync m16n8k16 GEMM, 128xBN tile, BK=32, double-buffered, 8 warps.
// Fragment loads via ldmatrix (x4/x2) -- conflict-free on stride-20 rows.
// MODE 0: con1 = relu([Con_t|Con_{t-1}] @ wp^T + bp)  M=158720, N=300, K=600, BN=160
// MODE 1: htF  = ht @ F1[300:600]^T + b1 (fp32)       M=16384,  N=200, K=300, BN=224
// MODE 2: wdyn from fc1=relu(Con1@F1[0:300]^T + htF)  M=163840, N=200, K=300, BN=224
// ---------------------------------------------------------------------------
template<int MODE>
__global__ __launch_bounds__(256) void mma_gemm(
    const float* __restrict__ bias,
    const float* __restrict__ x, const float* __restrict__ AngleM,
    const float* __restrict__ F2, const float* __restrict__ b2)
{
  constexpr int BN   = (MODE==0) ? 160 : 224;
  constexpr int NI   = (MODE==0) ? 5   : 7;
  constexpr int NP   = NI/2;                    // ldmatrix x4 pairs (2 / 3)
  constexpr int WNW  = BN/4;
  constexpr int TOTB = BN*4;
  constexpr int BIT  = (TOTB + 255)/256;
  constexpr int NCHv = (MODE==0) ? 19 : 10;
  constexpr int KLEN = (MODE==0) ? 600 : 300;
  constexpr int LDB  = (MODE==0) ? 600 : 304;
  const int Ntot = (MODE==0) ? 300 : 200;

  extern __shared__ uint32_t smw[];
  uint32_t* AsW = smw;                          // [2][128][20]
  uint32_t* BsW = smw + 2*BM*20;                // [2][BN][20]
  __shared__ float sF2[224];
  __shared__ float sdyn[BM];

  const __nv_bfloat16* Bsrc = (MODE==0) ? g_wpB : ((MODE==1) ? g_F1Bb : g_F1Ba);

  int tid = threadIdx.x, lane = tid&31, wid = tid>>5;
  int warpM = wid>>2, warpN = wid&3;
  int g = lane>>2, tg = lane&3;
  int m0 = blockIdx.y*BM, n0 = blockIdx.x*BN;

  uint32_t sA_base = (uint32_t)__cvta_generic_to_shared(AsW);
  uint32_t sB_base = (uint32_t)__cvta_generic_to_shared(BsW);
  // ldmatrix lane->address components
  int aRow  = lane & 15;            // A: m within 16
  int aK4   = (lane >> 4) * 4;      // A: k-word offset (0 or 4)
  int bseg  = lane >> 3;
  int bRow4 = ((bseg & 2) << 2) + (lane & 7);   // B x4: n within 16
  int bK4   = (bseg & 1) * 4;                   // B x4: k-word offset
  int bRow2 = lane & 7;                         // B x2: n within 8
  int bK2   = ((lane >> 3) & 1) * 4;            // (lanes>=16 unused)

  if (MODE==2){
    if (tid < 224) sF2[tid] = (tid < 200) ? F2[tid] : 0.f;
    if (tid < BM)  sdyn[tid] = 0.f;
  }

  int am[4], au[4]; long aoff0[4];
  #pragma unroll
  for (int j=0;j<4;j++){
    int idx = tid + j*256;
    am[j] = idx>>3; au[j] = idx&7;
    aoff0[j] = (long)(m0 + am[j])*300;
  }
  int bn[BIT], bq[BIT];
  #pragma unroll
  for (int j=0;j<BIT;j++){
    int idx = tid + j*256;
    bn[j] = idx>>2; bq[j] = idx&3;
  }

  float acc[4][NI][4];
  #pragma unroll
  for(int i=0;i<4;i++) for(int jn=0;jn<NI;jn++) for(int r=0;r<4;r++) acc[i][jn][r]=0.f;

  uint2 aR[4]; uint4 bR[BIT];
  const uint2 z2 = make_uint2(0,0);
  const uint4 z4c = make_uint4(0,0,0,0);

  auto fetchA = [&](int j, int k0)->uint2{
    int kk = k0 + au[j]*4;
    if (MODE==0){
      if (kk < 300)      return *(const uint2*)(g_Con + 1536000 + aoff0[j] + kk);
      else if (kk < 600) return *(const uint2*)(g_Con + aoff0[j] + (kk-300));
      return z2;
    } else if (MODE==1){
      if (kk < 300) return *(const uint2*)(g_ht + aoff0[j] + kk);
      return z2;
    } else {
      if (kk < 300) return *(const uint2*)(g_Con1 + aoff0[j] + kk);
      return z2;
    }
  };
  auto fetchB = [&](int j, int k0)->uint4{
    int idx = bn[j]*4 + bq[j];
    int kk = k0 + bq[j]*8;
    int n  = n0 + bn[j];
    if (idx < TOTB && kk < KLEN && n < Ntot)
      return *(const uint4*)(Bsrc + (long)n*LDB + kk);
    return z4c;
  };
  auto stash = [&](int buf){
    #pragma unroll
    for (int j=0;j<4;j++)
      *(uint2*)&AsW[(buf*BM + am[j])*20 + au[j]*2] = aR[j];
    #pragma unroll
    for (int j=0;j<BIT;j++){
      int idx = bn[j]*4 + bq[j];
      if (idx < TOTB)
        *(uint4*)&BsW[(buf*BN + bn[j])*20 + bq[j]*4] = bR[j];
    }
  };

  #pragma unroll
  for (int j=0;j<4;j++)  aR[j] = fetchA(j, 0);
  #pragma unroll
  for (int j=0;j<BIT;j++) bR[j] = fetchB(j, 0);
  stash(0);
  __syncthreads();

  for (int c=0; c<NCHv; c++){
    int buf = c & 1;
    if (c+1 < NCHv){
      int k0 = (c+1)*32;
      #pragma unroll
      for (int j=0;j<4;j++)  aR[j] = fetchA(j, k0);
      #pragma unroll
      for (int j=0;j<BIT;j++) bR[j] = fetchB(j, k0);
    }
    #pragma unroll
    for (int ks=0; ks<2; ks++){
      int kw = ks*8;
      uint32_t af[4][4];
      #pragma unroll
      for (int mi=0; mi<4; mi++){
        int mr = warpM*64 + mi*16;
        uint32_t sa = sA_base + ((buf*BM + mr + aRow)*20 + kw + aK4)*4;
        ldsm_x4(af[mi][0], af[mi][1], af[mi][2], af[mi][3], sa);
      }
      uint32_t bfr[NI][2];
      #pragma unroll
      for (int p=0; p<NP; p++){
        int nc = warpN*WNW + p*16;
        uint32_t sb = sB_base + ((buf*BN + nc + bRow4)*20 + kw + bK4)*4;
        ldsm_x4(bfr[2*p][0], bfr[2*p][1], bfr[2*p+1][0], bfr[2*p+1][1], sb);
      }
      { // odd last ni
        int nc = warpN*WNW + (NI-1)*8;
        uint32_t sb = sB_base + ((buf*BN + nc + bRow2)*20 + kw + bK2)*4;
        ldsm_x2(bfr[NI-1][0], bfr[NI-1][1], sb);
      }
      #pragma unroll
      for (int mi=0; mi<4; mi++)
        #pragma unroll
        for (int ni=0; ni<NI; ni++){
          asm volatile(
            "mma.sync.aligned.m16n8k16.row.col.f32.bf16.bf16.f32 "
            "{%0,%1,%2,%3}, {%4,%5,%6,%7}, {%8,%9}, {%0,%1,%2,%3};"
            : "+f"(acc[mi][ni][0]), "+f"(acc[mi][ni][1]),
              "+f"(acc[mi][ni][2]), "+f"(acc[mi][ni][3])
            : "r"(af[mi][0]), "r"(af[mi][1]), "r"(af[mi][2]), "r"(af[mi][3]),
              "r"(bfr[ni][0]), "r"(bfr[ni][1]));
        }
    }
    if (c+1 < NCHv) stash(buf ^ 1);
    __syncthreads();
  }

  if (MODE==0){
    __nv_bfloat16* Cptr = g_Con1 + 1536000;
    #pragma unroll
    for (int mi=0; mi<4; mi++){
      #pragma unroll
      for (int ni=0; ni<NI; ni++){
        int row = m0 + warpM*64 + mi*16 + g;
        int col = n0 + warpN*WNW + ni*8 + tg*2;
        if (col < Ntot){
          float b0v = bias[col], b1v = bias[col+1];
          __nv_bfloat162 p0 = __floats2bfloat162_rn(
              fmaxf(acc[mi][ni][0] + b0v, 0.f), fmaxf(acc[mi][ni][1] + b1v, 0.f));
          __nv_bfloat162 p1 = __floats2bfloat162_rn(
              fmaxf(acc[mi][ni][2] + b0v, 0.f), fmaxf(acc[mi][ni][3] + b1v, 0.f));
          *(__nv_bfloat162*)&Cptr[(long)row*300 + col]     = p0;
          *(__nv_bfloat162*)&Cptr[(long)(row+8)*300 + col] = p1;
        }
      }
    }
  } else if (MODE==1){
    #pragma unroll
    for (int mi=0; mi<4; mi++){
      #pragma unroll
      for (int ni=0; ni<NI; ni++){
        int row = m0 + warpM*64 + mi*16 + g;
        int col = n0 + warpN*WNW + ni*8 + tg*2;
        if (col < 200){
          float b0v = bias[col], b1v = bias[col+1];
          *(float2*)&g_htF[(long)row*200 + col] =
              make_float2(acc[mi][ni][0] + b0v, acc[mi][ni][1] + b1v);
          *(float2*)&g_htF[(long)(row+8)*200 + col] =
              make_float2(acc[mi][ni][2] + b0v, acc[mi][ni][3] + b1v);
        }
      }
    }
  } else {
    // fused wdyn: fc1 = relu(acc + htF[row/10]); dot with F2[:200]
    #pragma unroll
    for (int mi=0; mi<4; mi++){
      int row  = m0 + warpM*64 + mi*16 + g;
      long hb0 = (long)(row/10)*200;
      long hb1 = (long)((row+8)/10)*200;
      float p0 = 0.f, p1 = 0.f;
      #pragma unroll
      for (int ni=0; ni<NI; ni++){
        int col = n0 + warpN*WNW + ni*8 + tg*2;
        if (col < 200){
          float h00 = g_htF[hb0+col], h01 = g_htF[hb0+col+1];
          float h10 = g_htF[hb1+col], h11 = g_htF[hb1+col+1];
          float f20 = sF2[col], f21 = sF2[col+1];
          p0 = fmaf(fmaxf(acc[mi][ni][0] + h00, 0.f), f20, p0);
          p0 = fmaf(fmaxf(acc[mi][ni][1] + h01, 0.f), f21, p0);
          p1 = fmaf(fmaxf(acc[mi][ni][2] + h10, 0.f), f20, p1);
          p1 = fmaf(fmaxf(acc[mi][ni][3] + h11, 0.f), f21, p1);
        }
      }
      p0 += __shfl_xor_sync(0xffffffffu, p0, 1);
      p0 += __shfl_xor_sync(0xffffffffu, p0, 2);
      p1 += __shfl_xor_sync(0xffffffffu, p1, 1);
      p1 += __shfl_xor_sync(0xffffffffu, p1, 2);
      if (tg == 0){
        int lr = warpM*64 + mi*16 + g;
        atomicAdd(&sdyn[lr], p0);
        atomicAdd(&sdyn[lr+8], p1);
      }
    }
    __syncthreads();
    if (tid < BM){
      int r = m0 + tid;
      int tb = r/10, k = r - tb*10;
      int t = tb>>9, b = tb&511;
      const float* xb = x + (b*32+t)*280;
      float x8  = xb[80+k];
      float ang = fabsf(xb[100+k] - AngleM[k]) * (1.f/360.f);
      float w = sdyn[tid] + x8*F2[200] + ang*F2[201] + b2[0];
      g_wdyn[r] = fmaxf(w, 0.f);
    }
  }
}

__global__ void denom_kernel(){
  int tb = blockIdx.x*blockDim.x+threadIdx.x;
  if (tb >= TB) return;
  float s=0.f;
  #pragma unroll
  for(int k=0;k<10;k++) s += __expf(g_wdyn[tb*10+k]);
  g_den[tb]=s;
}

// ---------------------------------------------------------------------------
// final v2: 8 tb per block. Phase 1: wa gather + cat (per warp). Phase 2:
// 200 threads x 4 output cols each (float4 fuse1), fd from ff, reduce.
// ---------------------------------------------------------------------------
__global__ __launch_bounds__(256) void final2_kernel(
    const float* __restrict__ x, const float* __restrict__ labels,
    const float* __restrict__ DisM, const float* __restrict__ fuse1,
    const float* __restrict__ biasf, const float* __restrict__ ff,
    const float* __restrict__ bff, const float* __restrict__ Wout,
    const float* __restrict__ biasout, const float* __restrict__ a,
    float* __restrict__ out, int out_size)
{
  __shared__ float sA[10];
  __shared__ float scat[8][304];
  __shared__ float sxw[8][17];
  __shared__ float smix[8][25];
  int tid = threadIdx.x, w = tid>>5, lane = tid&31;
  int tb = blockIdx.x*8 + w; int t = tb>>9, b = tb&511;

  if (tid==0){
    float d[10], mx=-1e30f;
    #pragma unroll
    for(int i=0;i<10;i++){ d[i]=DisM[i]; mx=fmaxf(mx,d[i]); }
    float s=0.f;
    #pragma unroll
    for(int i=0;i<10;i++){ float e=__expf(d[i]-mx); sA[i]=e; s+=e; }
    float inv = 1.f/s;
    #pragma unroll
    for(int i=0;i<10;i++) sA[i]*=inv;
  }
  __syncthreads();

  float wa_l = 0.f;
  if (lane<10){
    int j = b*10+lane;
    int ko = j>>9, bo = j&511;
    wa_l = __expf(g_wdyn[(t*512+bo)*10+ko]) / g_den[t*512+bo];
  }
  float wa[10];
  #pragma unroll
  for (int q=0;q<10;q++) wa[q] = __shfl_sync(0xffffffffu, wa_l, q);

  for (int h=lane; h<304; h+=32){
    float s=0.f;
    if (h<300){
      #pragma unroll
      for(int q=0;q<10;q++)
        s = fmaf(__bfloat162float(g_Con1[(long)(tb*10+q)*300+h]), wa[q], s);
    }
    scat[w][h]=s;
  }
  if (lane<17){
    const float* xp = x + (b*32+t)*280 + (11+lane)*10;
    float s=0.f;
    #pragma unroll
    for(int q=0;q<10;q++) s = fmaf(xp[q], sA[q], s);
    sxw[w][lane]=s;
  }
  __syncthreads();

  float aa = a[0];
  if (tid < 200){
    int w2 = tid/25, og = tid - (tid/25)*25, o0 = og*4;
    float4 fu = make_float4(biasf[o0], biasf[o0+1], biasf[o0+2], biasf[o0+3]);
    const float* sc = scat[w2];
    #pragma unroll 4
    for (int h=0; h<300; h++){
      float s = sc[h];
      float4 f4 = *(const float4*)&fuse1[h*100 + o0];
      fu.x = fmaf(s, f4.x, fu.x);
      fu.y = fmaf(s, f4.y, fu.y);
      fu.z = fmaf(s, f4.z, fu.z);
      fu.w = fmaf(s, f4.w, fu.w);
    }
    float fuv[4] = {fu.x, fu.y, fu.z, fu.w};
    float part = 0.f;
    #pragma unroll
    for (int jo=0;jo<4;jo++){
      int o = o0+jo;
      float fd = bff[o];
      #pragma unroll
      for (int f=0;f<17;f++) fd = fmaf(ff[o*17+f], sxw[w2][f], fd);
      part += (aa*fuv[jo] + (1.f-aa)*fd) * Wout[o];
    }
    smix[w2][og] = part;
  }
  __syncthreads();
  if (tid < 8){
    int tb2 = blockIdx.x*8 + tid; int t2 = tb2>>9, b2 = tb2&511;
    float s = biasout[0];
    #pragma unroll
    for (int og=0; og<25; og++) s += smix[tid][og];
    out[t2*512+b2] = s;
    if (out_size >= 2*TB) out[TB + t2*512+b2] = labels[b2*32+t2];
  }
}

// ---------------------------------------------------------------------------
extern "C" void kernel_launch(void* const* d_in, const int* in_sizes, int n_in,
                              void* d_out, int out_size)
{
  const float* x      = (const float*)d_in[0];
  const float* labels = (const float*)d_in[1];
  const float* extras = (const float*)d_in[2];
  const float* DisM   = (const float*)d_in[3];
  const float* AngleM = (const float*)d_in[4];
  const float* Wih    = (const float*)d_in[5];
  const float* b_ih   = (const float*)d_in[6];
  const float* b_hh   = (const float*)d_in[7];
  const float* Wt     = (const float*)d_in[8];
  const float* bt_ih  = (const float*)d_in[9];
  const float* bt_hh  = (const float*)d_in[10];
  const float* wp     = (const float*)d_in[11];
  const float* bp     = (const float*)d_in[12];
  const float* F1     = (const float*)d_in[13];
  const float* b1     = (const float*)d_in[14];
  const float* F2     = (const float*)d_in[15];
  const float* b2     = (const float*)d_in[16];
  const float* ff     = (const float*)d_in[17];
  const float* bff    = (const float*)d_in[18];
  const float* fuse1  = (const float*)d_in[19];
  const float* biasf  = (const float*)d_in[20];
  const float* Wout   = (const float*)d_in[21];
  const float* biasout= (const float*)d_in[22];
  const float* a      = (const float*)d_in[23];
  float* out = (float*)d_out;

  // dyn smem (bytes): MODE0 = (2*128*20 + 2*160*20)*4 = 46080
  //                   MODE1/2 = (2*128*20 + 2*224*20)*4 = 56320
  cudaFuncSetAttribute((const void*)mma_gemm<0>,
                       cudaFuncAttributeMaxDynamicSharedMemorySize, 57344);
  cudaFuncSetAttribute((const void*)mma_gemm<1>,
                       cudaFuncAttributeMaxDynamicSharedMemorySize, 57344);
  cudaFuncSetAttribute((const void*)mma_gemm<2>,
                       cudaFuncAttributeMaxDynamicSharedMemorySize, 57344);

  round_weights<<<(180000+255)/256,256>>>(wp, F1);
  cells_kernel<<<dim3(512,10),320>>>(x, Wih, b_ih, b_hh);
  target_kernel<<<(TB*300+255)/256,256>>>(extras, Wt, bt_ih, bt_hh);
  copy_con0<<<750,256>>>();
  // con1 = relu([Con_t|Con_{t-1}] @ wp^T + bp)  M=158720 (1240), N=300 (2 x 160)
  mma_gemm<0><<<dim3(2,1240),256,46080>>>(bp, nullptr, nullptr, nullptr, nullptr);
  // htF = ht @ F1[300:600]^T + b1               M=16384 (128), N=200 (1 x 224)
  mma_gemm<1><<<dim3(1,128),256,56320>>>(b1, nullptr, nullptr, nullptr, nullptr);
  // wdyn via fc1 = relu(Con1 @ F1[0:300]^T + htF)  M=163840 (1280)
  mma_gemm<2><<<dim3(1,1280),256,56320>>>(nullptr, x, AngleM, F2, b2);
  denom_kernel<<<TB/256, 256>>>();
  final2_kernel<<<TB/8, 256>>>(x, labels, DisM, fuse1, biasf, ff, bff,
                               Wout, biasout, a, out, out_size);
}

// round 13
// speedup vs baseline: 5.5021x; 1.1478x over previous
#include <cuda_runtime.h>
#include <cuda_bf16.h>
#include <cstdint>

// Shapes
#define T_DIM 32
#define B_DIM 512
#define H_DIM 300
#define TB    16384          // T*B
#define NROWS 163840         // TB*10

#define BM 128

// Scratch (device globals — no allocation)
__device__ __align__(16) __nv_bfloat16 g_Con [NROWS*300]; // cells out [t,b,k,h]
__device__ __align__(16) __nv_bfloat16 g_Con1[NROWS*300]; // con1
__device__ __align__(16) __nv_bfloat16 g_ht  [TB*300];    // htarget
__device__ __align__(16) __nv_bfloat16 g_wpB [300*600+16];// wp  [n][k] bf16
__device__ __align__(16) __nv_bfloat16 g_F1Ba[200*304];   // F1^T[:,0:300]  stride 304
__device__ __align__(16) __nv_bfloat16 g_F1Bb[200*304];   // F1^T[:,300:600] stride 304
__device__ float g_htF [TB*200];     // ht @ F1[300:600] + b1 (fp32)
__device__ float g_wdyn[NROWS];
__device__ float g_den [TB];

__device__ __forceinline__ float ftanh(float x){
  float r; asm("tanh.approx.f32 %0, %1;" : "=f"(r) : "f"(x)); return r;
}
__device__ __forceinline__ float fsig(float x){
  return fmaf(ftanh(0.5f*x), 0.5f, 0.5f);
}
// odd poly tanh for |u| <= 1 (arg is sigma*tanh product, always in (-1,1))
__device__ __forceinline__ float ptanh1(float u){
  float u2 = u*u;
  float p = fmaf(-0.0344250f, u2, 0.1273500f);
  p = fmaf(p, u2, -0.3304800f);
  p = fmaf(p, u2,  0.9998997f);
  return u*p;
}
__device__ __forceinline__ void ldsm_x4(uint32_t& r0,uint32_t& r1,uint32_t& r2,uint32_t& r3,
                                        uint32_t saddr){
  asm volatile("ldmatrix.sync.aligned.m8n8.x4.shared.b16 {%0,%1,%2,%3}, [%4];"
               : "=r"(r0),"=r"(r1),"=r"(r2),"=r"(r3) : "r"(saddr));
}
__device__ __forceinline__ void ldsm_x2(uint32_t& r0,uint32_t& r1, uint32_t saddr){
  asm volatile("ldmatrix.sync.aligned.m8n8.x2.shared.b16 {%0,%1}, [%2];"
               : "=r"(r0),"=r"(r1) : "r"(saddr));
}

// wp [300][600] -> bf16   (split from round_weights for profiling slot alignment)
__global__ void round_wp(const float* __restrict__ wp){
  int i = blockIdx.x*blockDim.x+threadIdx.x;
  if (i < 180000) g_wpB[i] = __float2bfloat16(wp[i]);
}
// F1 [600][200] -> two transposed halves, stride 304
__global__ void round_F1(const float* __restrict__ F1){
  int i = blockIdx.x*blockDim.x+threadIdx.x;
  if (i < 60800){
    int n = i/304, kk = i - n*304;
    g_F1Ba[i] = (kk<300) ? __float2bfloat16(F1[kk*200 + n])       : __nv_bfloat16(0.f);
    g_F1Bb[i] = (kk<300) ? __float2bfloat16(F1[(300+kk)*200 + n]) : __nv_bfloat16(0.f);
  }
}

// ---------------------------------------------------------------------------
// cells v3: weights in regs, block x-slice staged to smem (kills redundant
// LDG broadcast), outer tanh -> poly (3 MUFU/output).
// ---------------------------------------------------------------------------
__global__ __launch_bounds__(352) void cells_kernel(
    const float* __restrict__ x, const float* __restrict__ Wih,
    const float* __restrict__ bih, const float* __restrict__ bhh)
{
  int k = blockIdx.y;
  __shared__ float sW[9900];
  __shared__ float sx[352];          // 32 tb x 11 inputs
  int tid = threadIdx.x;
  int base = k*13200;
  for (int idx=tid; idx<3300; idx+=352){
    sW[idx]      = Wih[base + idx];          // gate i rows 0..299
    sW[3300+idx] = Wih[base + 6600 + idx];   // gate g rows 600..899
    sW[6600+idx] = Wih[base + 9900 + idx];   // gate o rows 900..1199
  }
  int tb0 = blockIdx.x*32;
  {
    int tbl = tid/11, i = tid - tbl*11;      // tid < 352 covers 32x11
    int tb = tb0 + tbl;
    int t = tb>>9, b = tb & 511;
    sx[tid] = __ldg(x + ((b*32+t)*28 + i)*10 + k);
  }
  __syncthreads();
  int h = tid;
  float wi[11], wg[11], wo[11], bi=0.f, bg=0.f, bo=0.f;
  if (h < 300){
    #pragma unroll
    for (int i=0;i<11;i++){
      wi[i] = sW[h*11+i];
      wg[i] = sW[3300+h*11+i];
      wo[i] = sW[6600+h*11+i];
    }
    bi = bih[k*1200+h]     + bhh[k*1200+h];
    bg = bih[k*1200+600+h] + bhh[k*1200+600+h];
    bo = bih[k*1200+900+h] + bhh[k*1200+900+h];
  }
  if (h < 300){
    for (int tbl=0; tbl<32; tbl++){
      float xs[11];
      #pragma unroll
      for(int i=0;i<11;i++) xs[i] = sx[tbl*11+i];   // broadcast LDS
      float gi=bi, gg=bg, go=bo;
      #pragma unroll
      for(int i=0;i<11;i++){
        gi = fmaf(wi[i], xs[i], gi);
        gg = fmaf(wg[i], xs[i], gg);
        go = fmaf(wo[i], xs[i], go);
      }
      float u = fsig(gi)*ftanh(gg);           // |u| < 1
      g_Con[((tb0+tbl)*10+k)*300+h] = __float2bfloat16(fsig(go)*ptanh1(u));
    }
  }
}

// ---------------------------------------------------------------------------
// target cell (outputs bf16); outer tanh -> poly
// ---------------------------------------------------------------------------
__global__ __launch_bounds__(256) void target_kernel(
    const float* __restrict__ extras, const float* __restrict__ Wt,
    const float* __restrict__ bti, const float* __restrict__ bth)
{
  int idx = blockIdx.x*blockDim.x+threadIdx.x;
  if (idx >= TB*300) return;
  int tb = idx/300, h = idx - tb*300;
  int t = tb>>9, b = tb&511;
  const float* e = extras + (b*32+t)*4;
  float e0=e[0], e1=e[1], e2=e[2], e3=e[3];
  const float* w = Wt + h*4;
  float gi = w[0]*e0+w[1]*e1+w[2]*e2+w[3]*e3 + bti[h]+bth[h];
  w = Wt + (600+h)*4;
  float gg = w[0]*e0+w[1]*e1+w[2]*e2+w[3]*e3 + bti[600+h]+bth[600+h];
  w = Wt + (900+h)*4;
  float go = w[0]*e0+w[1]*e1+w[2]*e2+w[3]*e3 + bti[900+h]+bth[900+h];
  float u = fsig(gi)*ftanh(gg);
  g_ht[idx] = __float2bfloat16(fsig(go)*ptanh1(u));
}

// t=0 rows: con1 = con0 (bf16 copy)
__global__ void copy_con0(){
  int i = blockIdx.x*blockDim.x+threadIdx.x;
  if (i < 192000) ((uint4*)g_Con1)[i] = ((const uint4*)g_Con)[i];
}

// ---------------------------------------------------------------------------
// bf16 mma.sync m16n8k16 GEMM, 128xBN tile, BK=32, double-buffered, 8 warps.
// Fragment loads via ldmatrix (x4/x2) -- conflict-free on stride-20 rows.
// MODE 0: con1 = relu([Con_t|Con_{t-1}] @ wp^T + bp)  M=158720, N=300, K=600, BN=160
// MODE 1: htF  = ht @ F1[300:600]^T + b1 (fp32)       M=16384,  N=200, K=300, BN=224
// MODE 2: wdyn from fc1=relu(Con1@F1[0:300]^T + htF)  M=163840, N=200, K=300, BN=224
// ---------------------------------------------------------------------------
template<int MODE>
__global__ __launch_bounds__(256) void mma_gemm(
    const float* __restrict__ bias,
    const float* __restrict__ x, const float* __restrict__ AngleM,
    const float* __restrict__ F2, const float* __restrict__ b2)
{
  constexpr int BN   = (MODE==0) ? 160 : 224;
  constexpr int NI   = (MODE==0) ? 5   : 7;
  constexpr int NP   = NI/2;
  constexpr int WNW  = BN/4;
  constexpr int TOTB = BN*4;
  constexpr int BIT  = (TOTB + 255)/256;
  constexpr int NCHv = (MODE==0) ? 19 : 10;
  constexpr int KLEN = (MODE==0) ? 600 : 300;
  constexpr int LDB  = (MODE==0) ? 600 : 304;
  const int Ntot = (MODE==0) ? 300 : 200;

  extern __shared__ uint32_t smw[];
  uint32_t* AsW = smw;                          // [2][128][20]
  uint32_t* BsW = smw + 2*BM*20;                // [2][BN][20]
  __shared__ float sF2[224];
  __shared__ float sdyn[BM];

  const __nv_bfloat16* Bsrc = (MODE==0) ? g_wpB : ((MODE==1) ? g_F1Bb : g_F1Ba);

  int tid = threadIdx.x, lane = tid&31, wid = tid>>5;
  int warpM = wid>>2, warpN = wid&3;
  int g = lane>>2, tg = lane&3;
  int m0 = blockIdx.y*BM, n0 = blockIdx.x*BN;

  uint32_t sA_base = (uint32_t)__cvta_generic_to_shared(AsW);
  uint32_t sB_base = (uint32_t)__cvta_generic_to_shared(BsW);
  int aRow  = lane & 15;
  int aK4   = (lane >> 4) * 4;
  int bseg  = lane >> 3;
  int bRow4 = ((bseg & 2) << 2) + (lane & 7);
  int bK4   = (bseg & 1) * 4;
  int bRow2 = lane & 7;
  int bK2   = ((lane >> 3) & 1) * 4;

  if (MODE==2){
    if (tid < 224) sF2[tid] = (tid < 200) ? F2[tid] : 0.f;
    if (tid < BM)  sdyn[tid] = 0.f;
  }

  int am[4], au[4]; long aoff0[4];
  #pragma unroll
  for (int j=0;j<4;j++){
    int idx = tid + j*256;
    am[j] = idx>>3; au[j] = idx&7;
    aoff0[j] = (long)(m0 + am[j])*300;
  }
  int bn[BIT], bq[BIT];
  #pragma unroll
  for (int j=0;j<BIT;j++){
    int idx = tid + j*256;
    bn[j] = idx>>2; bq[j] = idx&3;
  }

  float acc[4][NI][4];
  #pragma unroll
  for(int i=0;i<4;i++) for(int jn=0;jn<NI;jn++) for(int r=0;r<4;r++) acc[i][jn][r]=0.f;

  uint2 aR[4]; uint4 bR[BIT];
  const uint2 z2 = make_uint2(0,0);
  const uint4 z4c = make_uint4(0,0,0,0);

  auto fetchA = [&](int j, int k0)->uint2{
    int kk = k0 + au[j]*4;
    if (MODE==0){
      if (kk < 300)      return *(const uint2*)(g_Con + 1536000 + aoff0[j] + kk);
      else if (kk < 600) return *(const uint2*)(g_Con + aoff0[j] + (kk-300));
      return z2;
    } else if (MODE==1){
      if (kk < 300) return *(const uint2*)(g_ht + aoff0[j] + kk);
      return z2;
    } else {
      if (kk < 300) return *(const uint2*)(g_Con1 + aoff0[j] + kk);
      return z2;
    }
  };
  auto fetchB = [&](int j, int k0)->uint4{
    int idx = bn[j]*4 + bq[j];
    int kk = k0 + bq[j]*8;
    int n  = n0 + bn[j];
    if (idx < TOTB && kk < KLEN && n < Ntot)
      return *(const uint4*)(Bsrc + (long)n*LDB + kk);
    return z4c;
  };
  auto stash = [&](int buf){
    #pragma unroll
    for (int j=0;j<4;j++)
      *(uint2*)&AsW[(buf*BM + am[j])*20 + au[j]*2] = aR[j];
    #pragma unroll
    for (int j=0;j<BIT;j++){
      int idx = bn[j]*4 + bq[j];
      if (idx < TOTB)
        *(uint4*)&BsW[(buf*BN + bn[j])*20 + bq[j]*4] = bR[j];
    }
  };

  #pragma unroll
  for (int j=0;j<4;j++)  aR[j] = fetchA(j, 0);
  #pragma unroll
  for (int j=0;j<BIT;j++) bR[j] = fetchB(j, 0);
  stash(0);
  __syncthreads();

  for (int c=0; c<NCHv; c++){
    int buf = c & 1;
    if (c+1 < NCHv){
      int k0 = (c+1)*32;
      #pragma unroll
      for (int j=0;j<4;j++)  aR[j] = fetchA(j, k0);
      #pragma unroll
      for (int j=0;j<BIT;j++) bR[j] = fetchB(j, k0);
    }
    #pragma unroll
    for (int ks=0; ks<2; ks++){
      int kw = ks*8;
      uint32_t af[4][4];
      #pragma unroll
      for (int mi=0; mi<4; mi++){
        int mr = warpM*64 + mi*16;
        uint32_t sa = sA_base + ((buf*BM + mr + aRow)*20 + kw + aK4)*4;
        ldsm_x4(af[mi][0], af[mi][1], af[mi][2], af[mi][3], sa);
      }
      uint32_t bfr[NI][2];
      #pragma unroll
      for (int p=0; p<NP; p++){
        int nc = warpN*WNW + p*16;
        uint32_t sb = sB_base + ((buf*BN + nc + bRow4)*20 + kw + bK4)*4;
        ldsm_x4(bfr[2*p][0], bfr[2*p][1], bfr[2*p+1][0], bfr[2*p+1][1], sb);
      }
      {
        int nc = warpN*WNW + (NI-1)*8;
        uint32_t sb = sB_base + ((buf*BN + nc + bRow2)*20 + kw + bK2)*4;
        ldsm_x2(bfr[NI-1][0], bfr[NI-1][1], sb);
      }
      #pragma unroll
      for (int mi=0; mi<4; mi++)
        #pragma unroll
        for (int ni=0; ni<NI; ni++){
          asm volatile(
            "mma.sync.aligned.m16n8k16.row.col.f32.bf16.bf16.f32 "
            "{%0,%1,%2,%3}, {%4,%5,%6,%7}, {%8,%9}, {%0,%1,%2,%3};"
            : "+f"(acc[mi][ni][0]), "+f"(acc[mi][ni][1]),
              "+f"(acc[mi][ni][2]), "+f"(acc[mi][ni][3])
            : "r"(af[mi][0]), "r"(af[mi][1]), "r"(af[mi][2]), "r"(af[mi][3]),
              "r"(bfr[ni][0]), "r"(bfr[ni][1]));
        }
    }
    if (c+1 < NCHv) stash(buf ^ 1);
    __syncthreads();
  }

  if (MODE==0){
    __nv_bfloat16* Cptr = g_Con1 + 1536000;
    #pragma unroll
    for (int mi=0; mi<4; mi++){
      #pragma unroll
      for (int ni=0; ni<NI; ni++){
        int row = m0 + warpM*64 + mi*16 + g;
        int col = n0 + warpN*WNW + ni*8 + tg*2;
        if (col < Ntot){
          float b0v = bias[col], b1v = bias[col+1];
          __nv_bfloat162 p0 = __floats2bfloat162_rn(
              fmaxf(acc[mi][ni][0] + b0v, 0.f), fmaxf(acc[mi][ni][1] + b1v, 0.f));
          __nv_bfloat162 p1 = __floats2bfloat162_rn(
              fmaxf(acc[mi][ni][2] + b0v, 0.f), fmaxf(acc[mi][ni][3] + b1v, 0.f));
          *(__nv_bfloat162*)&Cptr[(long)row*300 + col]     = p0;
          *(__nv_bfloat162*)&Cptr[(long)(row+8)*300 + col] = p1;
        }
      }
    }
  } else if (MODE==1){
    #pragma unroll
    for (int mi=0; mi<4; mi++){
      #pragma unroll
      for (int ni=0; ni<NI; ni++){
        int row = m0 + warpM*64 + mi*16 + g;
        int col = n0 + warpN*WNW + ni*8 + tg*2;
        if (col < 200){
          float b0v = bias[col], b1v = bias[col+1];
          *(float2*)&g_htF[(long)row*200 + col] =
              make_float2(acc[mi][ni][0] + b0v, acc[mi][ni][1] + b1v);
          *(float2*)&g_htF[(long)(row+8)*200 + col] =
              make_float2(acc[mi][ni][2] + b0v, acc[mi][ni][3] + b1v);
        }
      }
    }
  } else {
    #pragma unroll
    for (int mi=0; mi<4; mi++){
      int row  = m0 + warpM*64 + mi*16 + g;
      long hb0 = (long)(row/10)*200;
      long hb1 = (long)((row+8)/10)*200;
      float p0 = 0.f, p1 = 0.f;
      #pragma unroll
      for (int ni=0; ni<NI; ni++){
        int col = n0 + warpN*WNW + ni*8 + tg*2;
        if (col < 200){
          float h00 = g_htF[hb0+col], h01 = g_htF[hb0+col+1];
          float h10 = g_htF[hb1+col], h11 = g_htF[hb1+col+1];
          float f20 = sF2[col], f21 = sF2[col+1];
          p0 = fmaf(fmaxf(acc[mi][ni][0] + h00, 0.f), f20, p0);
          p0 = fmaf(fmaxf(acc[mi][ni][1] + h01, 0.f), f21, p0);
          p1 = fmaf(fmaxf(acc[mi][ni][2] + h10, 0.f), f20, p1);
          p1 = fmaf(fmaxf(acc[mi][ni][3] + h11, 0.f), f21, p1);
        }
      }
      p0 += __shfl_xor_sync(0xffffffffu, p0, 1);
      p0 += __shfl_xor_sync(0xffffffffu, p0, 2);
      p1 += __shfl_xor_sync(0xffffffffu, p1, 1);
      p1 += __shfl_xor_sync(0xffffffffu, p1, 2);
      if (tg == 0){
        int lr = warpM*64 + mi*16 + g;
        atomicAdd(&sdyn[lr], p0);
        atomicAdd(&sdyn[lr+8], p1);
      }
    }
    __syncthreads();
    if (tid < BM){
      int r = m0 + tid;
      int tb = r/10, k = r - tb*10;
      int t = tb>>9, b = tb&511;
      const float* xb = x + (b*32+t)*280;
      float x8  = xb[80+k];
      float ang = fabsf(xb[100+k] - AngleM[k]) * (1.f/360.f);
      float w = sdyn[tid] + x8*F2[200] + ang*F2[201] + b2[0];
      g_wdyn[r] = fmaxf(w, 0.f);
    }
  }
}

__global__ void denom_kernel(){
  int tb = blockIdx.x*blockDim.x+threadIdx.x;
  if (tb >= TB) return;
  float s=0.f;
  #pragma unroll
  for(int k=0;k<10;k++) s += __expf(g_wdyn[tb*10+k]);
  g_den[tb]=s;
}

// ---------------------------------------------------------------------------
// final v2: 8 tb per block.
// ---------------------------------------------------------------------------
__global__ __launch_bounds__(256) void final2_kernel(
    const float* __restrict__ x, const float* __restrict__ labels,
    const float* __restrict__ DisM, const float* __restrict__ fuse1,
    const float* __restrict__ biasf, const float* __restrict__ ff,
    const float* __restrict__ bff, const float* __restrict__ Wout,
    const float* __restrict__ biasout, const float* __restrict__ a,
    float* __restrict__ out, int out_size)
{
  __shared__ float sA[10];
  __shared__ float scat[8][304];
  __shared__ float sxw[8][17];
  __shared__ float smix[8][25];
  int tid = threadIdx.x, w = tid>>5, lane = tid&31;
  int tb = blockIdx.x*8 + w; int t = tb>>9, b = tb&511;

  if (tid==0){
    float d[10], mx=-1e30f;
    #pragma unroll
    for(int i=0;i<10;i++){ d[i]=DisM[i]; mx=fmaxf(mx,d[i]); }
    float s=0.f;
    #pragma unroll
    for(int i=0;i<10;i++){ float e=__expf(d[i]-mx); sA[i]=e; s+=e; }
    float inv = 1.f/s;
    #pragma unroll
    for(int i=0;i<10;i++) sA[i]*=inv;
  }
  __syncthreads();

  float wa_l = 0.f;
  if (lane<10){
    int j = b*10+lane;
    int ko = j>>9, bo = j&511;
    wa_l = __expf(g_wdyn[(t*512+bo)*10+ko]) / g_den[t*512+bo];
  }
  float wa[10];
  #pragma unroll
  for (int q=0;q<10;q++) wa[q] = __shfl_sync(0xffffffffu, wa_l, q);

  for (int h=lane; h<304; h+=32){
    float s=0.f;
    if (h<300){
      #pragma unroll
      for(int q=0;q<10;q++)
        s = fmaf(__bfloat162float(g_Con1[(long)(tb*10+q)*300+h]), wa[q], s);
    }
    scat[w][h]=s;
  }
  if (lane<17){
    const float* xp = x + (b*32+t)*280 + (11+lane)*10;
    float s=0.f;
    #pragma unroll
    for(int q=0;q<10;q++) s = fmaf(xp[q], sA[q], s);
    sxw[w][lane]=s;
  }
  __syncthreads();

  float aa = a[0];
  if (tid < 200){
    int w2 = tid/25, og = tid - (tid/25)*25, o0 = og*4;
    float4 fu = make_float4(biasf[o0], biasf[o0+1], biasf[o0+2], biasf[o0+3]);
    const float* sc = scat[w2];
    #pragma unroll 4
    for (int h=0; h<300; h++){
      float s = sc[h];
      float4 f4 = *(const float4*)&fuse1[h*100 + o0];
      fu.x = fmaf(s, f4.x, fu.x);
      fu.y = fmaf(s, f4.y, fu.y);
      fu.z = fmaf(s, f4.z, fu.z);
      fu.w = fmaf(s, f4.w, fu.w);
    }
    float fuv[4] = {fu.x, fu.y, fu.z, fu.w};
    float part = 0.f;
    #pragma unroll
    for (int jo=0;jo<4;jo++){
      int o = o0+jo;
      float fd = bff[o];
      #pragma unroll
      for (int f=0;f<17;f++) fd = fmaf(ff[o*17+f], sxw[w2][f], fd);
      part += (aa*fuv[jo] + (1.f-aa)*fd) * Wout[o];
    }
    smix[w2][og] = part;
  }
  __syncthreads();
  if (tid < 8){
    int tb2 = blockIdx.x*8 + tid; int t2 = tb2>>9, b2 = tb2&511;
    float s = biasout[0];
    #pragma unroll
    for (int og=0; og<25; og++) s += smix[tid][og];
    out[t2*512+b2] = s;
    if (out_size >= 2*TB) out[TB + t2*512+b2] = labels[b2*32+t2];
  }
}

// ---------------------------------------------------------------------------
extern "C" void kernel_launch(void* const* d_in, const int* in_sizes, int n_in,
                              void* d_out, int out_size)
{
  const float* x      = (const float*)d_in[0];
  const float* labels = (const float*)d_in[1];
  const float* extras = (const float*)d_in[2];
  const float* DisM   = (const float*)d_in[3];
  const float* AngleM = (const float*)d_in[4];
  const float* Wih    = (const float*)d_in[5];
  const float* b_ih   = (const float*)d_in[6];
  const float* b_hh   = (const float*)d_in[7];
  const float* Wt     = (const float*)d_in[8];
  const float* bt_ih  = (const float*)d_in[9];
  const float* bt_hh  = (const float*)d_in[10];
  const float* wp     = (const float*)d_in[11];
  const float* bp     = (const float*)d_in[12];
  const float* F1     = (const float*)d_in[13];
  const float* b1     = (const float*)d_in[14];
  const float* F2     = (const float*)d_in[15];
  const float* b2     = (const float*)d_in[16];
  const float* ff     = (const float*)d_in[17];
  const float* bff    = (const float*)d_in[18];
  const float* fuse1  = (const float*)d_in[19];
  const float* biasf  = (const float*)d_in[20];
  const float* Wout   = (const float*)d_in[21];
  const float* biasout= (const float*)d_in[22];
  const float* a      = (const float*)d_in[23];
  float* out = (float*)d_out;

  cudaFuncSetAttribute((const void*)mma_gemm<0>,
                       cudaFuncAttributeMaxDynamicSharedMemorySize, 57344);
  cudaFuncSetAttribute((const void*)mma_gemm<1>,
                       cudaFuncAttributeMaxDynamicSharedMemorySize, 57344);
  cudaFuncSetAttribute((const void*)mma_gemm<2>,
                       cudaFuncAttributeMaxDynamicSharedMemorySize, 57344);

  // Launch order arranged so cells_kernel sits in the ncu capture slot (4th).
  round_wp<<<(180000+255)/256,256>>>(wp);
  round_F1<<<(60800+255)/256,256>>>(F1);
  target_kernel<<<(TB*300+255)/256,256>>>(extras, Wt, bt_ih, bt_hh);
  cells_kernel<<<dim3(512,10),352>>>(x, Wih, b_ih, b_hh);
  copy_con0<<<750,256>>>();
  // con1 = relu([Con_t|Con_{t-1}] @ wp^T + bp)  M=158720 (1240), N=300 (2 x 160)
  mma_gemm<0><<<dim3(2,1240),256,46080>>>(bp, nullptr, nullptr, nullptr, nullptr);
  // htF = ht @ F1[300:600]^T + b1               M=16384 (128), N=200 (1 x 224)
  mma_gemm<1><<<dim3(1,128),256,56320>>>(b1, nullptr, nullptr, nullptr, nullptr);
  // wdyn via fc1 = relu(Con1 @ F1[0:300]^T + htF)  M=163840 (1280)
  mma_gemm<2><<<dim3(1,1280),256,56320>>>(nullptr, x, AngleM, F2, b2);
  denom_kernel<<<TB/256, 256>>>();
  final2_kernel<<<TB/8, 256>>>(x, labels, DisM, fuse1, biasf, ff, bff,
                               Wout, biasout, a, out, out_size);
}